// round 6
// baseline (speedup 1.0000x reference)
#include <cuda_runtime.h>
#include <cuda_fp16.h>
#include <cstdint>
#include <cstddef>

#define DIM      768
#define NH       12
#define HD       64
#define BB       8
#define SEQ      1024
#define M_TOT    (BB * SEQ)          // 8192
#define QKV_N    (3 * DIM)           // 2304
#define ATT_SCALE 0.125f
#define QB       256                 // q rows per attention CTA

// ---------------------------------------------------------------------------
// Scratch planes (fp16 hi/lo splits). Device globals: allocation-free.
// ---------------------------------------------------------------------------
__device__ __half g_x_hi[(size_t)M_TOT * DIM];
__device__ __half g_x_lo[(size_t)M_TOT * DIM];
__device__ __half g_wqkv_hi[(size_t)QKV_N * DIM];
__device__ __half g_wqkv_lo[(size_t)QKV_N * DIM];
__device__ __half g_wproj_hi[(size_t)DIM * DIM];
__device__ __half g_qkv_hi[(size_t)M_TOT * QKV_N];
__device__ __half g_qkv_lo[(size_t)M_TOT * QKV_N];
__device__ __half g_att_hi[(size_t)M_TOT * DIM];
__device__ __half g_att_lo[(size_t)M_TOT * DIM];

// ---------------------------------------------------------------------------
// Helpers
// ---------------------------------------------------------------------------
__device__ __forceinline__ uint32_t sptr(const void* p) {
    return (uint32_t)__cvta_generic_to_shared(p);
}
__device__ __forceinline__ void cp16(void* dst, const void* src) {
    asm volatile("cp.async.cg.shared.global [%0], [%1], 16;"
                 :: "r"(sptr(dst)), "l"(src));
}
__device__ __forceinline__ void cp_commit() {
    asm volatile("cp.async.commit_group;");
}
template<int N>
__device__ __forceinline__ void cp_wait() {
    asm volatile("cp.async.wait_group %0;" :: "n"(N));
}
__device__ __forceinline__ void ldsm4(uint32_t r[4], uint32_t a) {
    asm volatile("ldmatrix.sync.aligned.m8n8.x4.shared.b16 {%0,%1,%2,%3}, [%4];"
                 : "=r"(r[0]), "=r"(r[1]), "=r"(r[2]), "=r"(r[3]) : "r"(a));
}
__device__ __forceinline__ void ldsm4t(uint32_t r[4], uint32_t a) {
    asm volatile("ldmatrix.sync.aligned.m8n8.x4.trans.shared.b16 {%0,%1,%2,%3}, [%4];"
                 : "=r"(r[0]), "=r"(r[1]), "=r"(r[2]), "=r"(r[3]) : "r"(a));
}
__device__ __forceinline__ void mma_f16(float c[4], const uint32_t a[4],
                                        uint32_t b0, uint32_t b1) {
    asm volatile(
        "mma.sync.aligned.m16n8k16.row.col.f32.f16.f16.f32 "
        "{%0,%1,%2,%3},{%4,%5,%6,%7},{%8,%9},{%0,%1,%2,%3};"
        : "+f"(c[0]), "+f"(c[1]), "+f"(c[2]), "+f"(c[3])
        : "r"(a[0]), "r"(a[1]), "r"(a[2]), "r"(a[3]), "r"(b0), "r"(b1));
}
__device__ __forceinline__ uint32_t pack_h(float a, float b) {
    __half2 t = __floats2half2_rn(a, b);
    return *reinterpret_cast<uint32_t*>(&t);
}
__device__ __forceinline__ void split_pair_h(float x, float y,
                                             uint32_t& hi, uint32_t& lo) {
    __half hx = __float2half_rn(x), hy = __float2half_rn(y);
    hi = (uint32_t)__half_as_ushort(hx) | ((uint32_t)__half_as_ushort(hy) << 16);
    lo = pack_h(x - __half2float(hx), y - __half2float(hy));
}

// ---------------------------------------------------------------------------
// fp32 -> fp16 hi/lo plane conversion
// ---------------------------------------------------------------------------
__global__ void split_planes(const float4* __restrict__ in,
                             uint2* __restrict__ hi, uint2* __restrict__ lo,
                             int n4) {
    int i = blockIdx.x * blockDim.x + threadIdx.x;
    if (i >= n4) return;
    float4 v = in[i];
    uint32_t h0, l0, h1, l1;
    split_pair_h(v.x, v.y, h0, l0);
    split_pair_h(v.z, v.w, h1, l1);
    hi[i] = make_uint2(h0, h1);
    if (lo) lo[i] = make_uint2(l0, l1);
}

// ---------------------------------------------------------------------------
// Split-fp16 tensor-core GEMM. CTA tile 128x256, warp tile 64x64 (2x4 warps),
// BK=32, 2-stage cp.async. NMMA=3: ah*bh+ah*bl+al*bh. NMMA=2: ah*bh+al*bh.
// ---------------------------------------------------------------------------
struct GemmSmem {
    __half Ah[2][128][40], Al[2][128][40];
    __half Bh[2][256][40], Bl[2][256][40];
};
extern __shared__ __align__(1024) char smem_raw[];

template<int NMMA>
__device__ __forceinline__ void gemm_load_stage(
    GemmSmem& s, int st,
    const __half* __restrict__ Ah_g, const __half* __restrict__ Al_g,
    const __half* __restrict__ Bh_g, const __half* __restrict__ Bl_g,
    int row0, int col0, int K, int k0, int tid)
{
#pragma unroll
    for (int l = 0; l < 2; l++) {               // A: 512 slots per plane
        int idx = tid + 256 * l;
        int r = idx >> 2, p = idx & 3;
        cp16(&s.Ah[st][r][p * 8], &Ah_g[(size_t)(row0 + r) * K + k0 + p * 8]);
        cp16(&s.Al[st][r][p * 8], &Al_g[(size_t)(row0 + r) * K + k0 + p * 8]);
    }
#pragma unroll
    for (int l = 0; l < 4; l++) {               // B: 1024 slots per plane
        int idx = tid + 256 * l;
        int r = idx >> 2, p = idx & 3;
        cp16(&s.Bh[st][r][p * 8], &Bh_g[(size_t)(col0 + r) * K + k0 + p * 8]);
        if (NMMA == 3)
            cp16(&s.Bl[st][r][p * 8], &Bl_g[(size_t)(col0 + r) * K + k0 + p * 8]);
    }
}

template<bool SPLIT_OUT, int NMMA>
__global__ void __launch_bounds__(256, 1)
gemm_f16s(const __half* __restrict__ Ah_g,
          const __half* __restrict__ Al_g,
          const __half* __restrict__ Bh_g,
          const __half* __restrict__ Bl_g,
          const float* __restrict__ bias,
          __half* __restrict__ Ch,
          __half* __restrict__ Cl,
          float* __restrict__ Cf,
          int M, int N, int K)
{
    GemmSmem& s = *reinterpret_cast<GemmSmem*>(smem_raw);

    const int tid  = threadIdx.x;
    const int lane = tid & 31;
    const int w    = tid >> 5;
    const int wm   = w & 1;       // 2 m-groups of 64
    const int wn   = w >> 1;      // 4 n-groups of 64
    const int row0 = blockIdx.y * 128;
    const int col0 = blockIdx.x * 256;

    float acc[4][8][4];
#pragma unroll
    for (int a = 0; a < 4; a++)
#pragma unroll
        for (int b = 0; b < 8; b++)
#pragma unroll
            for (int c = 0; c < 4; c++) acc[a][b][c] = 0.f;

    const int nk = K / 32;
    gemm_load_stage<NMMA>(s, 0, Ah_g, Al_g, Bh_g, Bl_g, row0, col0, K, 0, tid);
    cp_commit();

    for (int i = 0; i < nk; i++) {
        const int st = i & 1;
        if (i + 1 < nk) {
            gemm_load_stage<NMMA>(s, st ^ 1, Ah_g, Al_g, Bh_g, Bl_g,
                                  row0, col0, K, (i + 1) * 32, tid);
            cp_commit();
            cp_wait<1>();
        } else {
            cp_wait<0>();
        }
        __syncthreads();

#pragma unroll
        for (int kk = 0; kk < 32; kk += 16) {
            uint32_t ah[4][4], al[4][4];
#pragma unroll
            for (int mt = 0; mt < 4; mt++) {
                int r = 64 * wm + 16 * mt + (lane & 15);
                int c = kk + (lane >> 4) * 8;
                ldsm4(ah[mt], sptr(&s.Ah[st][r][c]));
                ldsm4(al[mt], sptr(&s.Al[st][r][c]));
            }
            uint32_t bh[4][4], bl[4][4];
#pragma unroll
            for (int nb = 0; nb < 4; nb++) {
                int r = 64 * wn + 16 * nb + (lane & 7) + (lane >> 4) * 8;
                int c = kk + ((lane >> 3) & 1) * 8;
                ldsm4(bh[nb], sptr(&s.Bh[st][r][c]));
                if (NMMA == 3) ldsm4(bl[nb], sptr(&s.Bl[st][r][c]));
            }
#pragma unroll
            for (int mt = 0; mt < 4; mt++) {
#pragma unroll
                for (int nb = 0; nb < 4; nb++) {
#pragma unroll
                    for (int h2 = 0; h2 < 2; h2++) {
                        float* cc = acc[mt][2 * nb + h2];
                        mma_f16(cc, ah[mt], bh[nb][2 * h2], bh[nb][2 * h2 + 1]);
                        if (NMMA == 3)
                            mma_f16(cc, ah[mt], bl[nb][2 * h2], bl[nb][2 * h2 + 1]);
                        mma_f16(cc, al[mt], bh[nb][2 * h2], bh[nb][2 * h2 + 1]);
                    }
                }
            }
        }
        __syncthreads();
    }

    // Epilogue
#pragma unroll
    for (int mt = 0; mt < 4; mt++) {
#pragma unroll
        for (int nt = 0; nt < 8; nt++) {
            int gr = row0 + 64 * wm + 16 * mt + (lane >> 2);
            int gc = col0 + 64 * wn + 8 * nt + 2 * (lane & 3);
            const float* cc = acc[mt][nt];
            if (SPLIT_OUT) {
                uint32_t h, l;
                split_pair_h(cc[0], cc[1], h, l);
                *reinterpret_cast<uint32_t*>(&Ch[(size_t)gr * N + gc]) = h;
                *reinterpret_cast<uint32_t*>(&Cl[(size_t)gr * N + gc]) = l;
                split_pair_h(cc[2], cc[3], h, l);
                *reinterpret_cast<uint32_t*>(&Ch[(size_t)(gr + 8) * N + gc]) = h;
                *reinterpret_cast<uint32_t*>(&Cl[(size_t)(gr + 8) * N + gc]) = l;
            } else {
                float b0 = bias[gc], b1 = bias[gc + 1];
                *reinterpret_cast<float2*>(&Cf[(size_t)gr * N + gc]) =
                    make_float2(cc[0] + b0, cc[1] + b1);
                *reinterpret_cast<float2*>(&Cf[(size_t)(gr + 8) * N + gc]) =
                    make_float2(cc[2] + b0, cc[3] + b1);
            }
        }
    }
}

// ---------------------------------------------------------------------------
// Fused quadratic-ReLU attention (unchanged from R5).
// ---------------------------------------------------------------------------
struct AttnSmem {
    __half Kh[2][128][72], Kl[2][128][72], Vh[2][128][72];
};

__device__ __forceinline__ void load_tile72_async(
    __half (*dst)[72], const __half* __restrict__ src, int tid)
{
#pragma unroll
    for (int l = 0; l < 4; l++) {
        int idx = tid + 256 * l;
        int r = idx >> 3, p = idx & 7;
        cp16(&dst[r][p * 8], &src[(size_t)r * QKV_N + p * 8]);
    }
}

__global__ void __launch_bounds__(256, 1)
attn_mma(const __half* __restrict__ qkv_hi,
         const __half* __restrict__ qkv_lo,
         const float* __restrict__ alpha,
         const float* __restrict__ beta,
         const float* __restrict__ gamma,
         __half* __restrict__ att_hi,
         __half* __restrict__ att_lo)
{
    AttnSmem& s = *reinterpret_cast<AttnSmem*>(smem_raw);
    const int tid  = threadIdx.x;
    const int lane = tid & 31;
    const int w    = tid >> 5;
    const int qt   = blockIdx.x;
    const int h    = blockIdx.y;
    const int b    = blockIdx.z;
    const int q0   = qt * QB;

    const float av = alpha[h], bv = beta[h], gv = gamma[h];
    const size_t base = (size_t)(b * SEQ) * QKV_N + h * HD;

    load_tile72_async(s.Kh[0], qkv_hi + base + DIM,     tid);
    load_tile72_async(s.Kl[0], qkv_lo + base + DIM,     tid);
    load_tile72_async(s.Vh[0], qkv_hi + base + 2 * DIM, tid);
    cp_commit();

    uint32_t qh[2][4][4], ql[2][4][4];
    {
        const int rb = b * SEQ + q0 + 32 * w + (lane >> 2);
        const int cb = h * HD + 2 * (lane & 3);
#pragma unroll
        for (int rg = 0; rg < 2; rg++) {
#pragma unroll
            for (int kc = 0; kc < 4; kc++) {
                size_t o00 = (size_t)(rb + 16 * rg) * QKV_N + cb + 16 * kc;
                size_t o10 = o00 + 8 * QKV_N;
                qh[rg][kc][0] = *reinterpret_cast<const uint32_t*>(&qkv_hi[o00]);
                qh[rg][kc][1] = *reinterpret_cast<const uint32_t*>(&qkv_hi[o10]);
                qh[rg][kc][2] = *reinterpret_cast<const uint32_t*>(&qkv_hi[o00 + 8]);
                qh[rg][kc][3] = *reinterpret_cast<const uint32_t*>(&qkv_hi[o10 + 8]);
                ql[rg][kc][0] = *reinterpret_cast<const uint32_t*>(&qkv_lo[o00]);
                ql[rg][kc][1] = *reinterpret_cast<const uint32_t*>(&qkv_lo[o10]);
                ql[rg][kc][2] = *reinterpret_cast<const uint32_t*>(&qkv_lo[o00 + 8]);
                ql[rg][kc][3] = *reinterpret_cast<const uint32_t*>(&qkv_lo[o10 + 8]);
            }
        }
    }

    float O[2][8][4];
#pragma unroll
    for (int rg = 0; rg < 2; rg++)
#pragma unroll
        for (int j = 0; j < 8; j++)
#pragma unroll
            for (int q = 0; q < 4; q++) O[rg][j][q] = 0.f;
    float rs[2][2] = {{0.f, 0.f}, {0.f, 0.f}};

    for (int kt = 0; kt < SEQ / 128; kt++) {
        const int st = kt & 1;
        if (kt + 1 < SEQ / 128) {
            const size_t koff = base + (size_t)((kt + 1) * 128) * QKV_N;
            load_tile72_async(s.Kh[st ^ 1], qkv_hi + koff + DIM,     tid);
            load_tile72_async(s.Kl[st ^ 1], qkv_lo + koff + DIM,     tid);
            load_tile72_async(s.Vh[st ^ 1], qkv_hi + koff + 2 * DIM, tid);
            cp_commit();
            cp_wait<1>();
        } else {
            cp_wait<0>();
        }
        __syncthreads();

#pragma unroll
        for (int rg = 0; rg < 2; rg++) {
            float S[16][4];
#pragma unroll
            for (int j = 0; j < 16; j++)
#pragma unroll
                for (int q = 0; q < 4; q++) S[j][q] = 0.f;

#pragma unroll
            for (int kc = 0; kc < 4; kc++) {
#pragma unroll
                for (int np = 0; np < 8; np++) {
                    uint32_t kh[4], kl[4];
                    int r = 16 * np + (lane & 7) + (lane >> 4) * 8;
                    int c = 16 * kc + ((lane >> 3) & 1) * 8;
                    ldsm4(kh, sptr(&s.Kh[st][r][c]));
                    ldsm4(kl, sptr(&s.Kl[st][r][c]));
                    mma_f16(S[2 * np + 0], qh[rg][kc], kh[0], kh[1]);
                    mma_f16(S[2 * np + 0], qh[rg][kc], kl[0], kl[1]);
                    mma_f16(S[2 * np + 0], ql[rg][kc], kh[0], kh[1]);
                    mma_f16(S[2 * np + 1], qh[rg][kc], kh[2], kh[3]);
                    mma_f16(S[2 * np + 1], qh[rg][kc], kl[2], kl[3]);
                    mma_f16(S[2 * np + 1], ql[rg][kc], kh[2], kh[3]);
                }
            }

#pragma unroll
            for (int j = 0; j < 16; j++) {
#pragma unroll
                for (int q = 0; q < 4; q++) {
                    float z = S[j][q] * ATT_SCALE;
                    float p = fmaf(fmaf(av, z, bv), z, gv);
                    S[j][q] = fmaxf(p, 0.f);
                }
                rs[rg][0] += S[j][0] + S[j][1];
                rs[rg][1] += S[j][2] + S[j][3];
            }

#pragma unroll
            for (int c8 = 0; c8 < 8; c8++) {
                uint32_t ph[4];
                ph[0] = pack_h(S[2 * c8][0],     S[2 * c8][1]);
                ph[1] = pack_h(S[2 * c8][2],     S[2 * c8][3]);
                ph[2] = pack_h(S[2 * c8 + 1][0], S[2 * c8 + 1][1]);
                ph[3] = pack_h(S[2 * c8 + 1][2], S[2 * c8 + 1][3]);
#pragma unroll
                for (int ep = 0; ep < 4; ep++) {
                    uint32_t vh[4];
                    int r = 16 * c8 + (lane & 7) + ((lane >> 3) & 1) * 8;
                    int c = 16 * ep + (lane >> 4) * 8;
                    ldsm4t(vh, sptr(&s.Vh[st][r][c]));
                    mma_f16(O[rg][2 * ep + 0], ph, vh[0], vh[1]);
                    mma_f16(O[rg][2 * ep + 1], ph, vh[2], vh[3]);
                }
            }
        }
        __syncthreads();
    }

#pragma unroll
    for (int rg = 0; rg < 2; rg++) {
        float r0 = rs[rg][0], r1 = rs[rg][1];
        r0 += __shfl_xor_sync(0xffffffffu, r0, 1);
        r0 += __shfl_xor_sync(0xffffffffu, r0, 2);
        r1 += __shfl_xor_sync(0xffffffffu, r1, 1);
        r1 += __shfl_xor_sync(0xffffffffu, r1, 2);
        const float inv0 = 1.f / (r0 + 1e-6f);
        const float inv1 = 1.f / (r1 + 1e-6f);

        const int row = b * SEQ + q0 + 32 * w + 16 * rg + (lane >> 2);
#pragma unroll
        for (int j = 0; j < 8; j++) {
            int ce = h * HD + 8 * j + 2 * (lane & 3);
            uint32_t hh, ll;
            split_pair_h(O[rg][j][0] * inv0, O[rg][j][1] * inv0, hh, ll);
            *reinterpret_cast<uint32_t*>(&att_hi[(size_t)row * DIM + ce]) = hh;
            *reinterpret_cast<uint32_t*>(&att_lo[(size_t)row * DIM + ce]) = ll;
            split_pair_h(O[rg][j][2] * inv1, O[rg][j][3] * inv1, hh, ll);
            *reinterpret_cast<uint32_t*>(&att_hi[(size_t)(row + 8) * DIM + ce]) = hh;
            *reinterpret_cast<uint32_t*>(&att_lo[(size_t)(row + 8) * DIM + ce]) = ll;
        }
    }
}

// ---------------------------------------------------------------------------
// Launch
// ---------------------------------------------------------------------------
extern "C" void kernel_launch(void* const* d_in, const int* in_sizes, int n_in,
                              void* d_out, int out_size)
{
    const float* x      = (const float*)d_in[0];
    const float* w_qkv  = (const float*)d_in[1];
    const float* w_proj = (const float*)d_in[2];
    const float* b_proj = (const float*)d_in[3];
    const float* alpha  = (const float*)d_in[4];
    const float* beta   = (const float*)d_in[5];
    const float* gamma  = (const float*)d_in[6];
    float* out = (float*)d_out;

    __half *xh, *xl, *wqh, *wql, *wph, *qh, *ql, *ah, *al;
    cudaGetSymbolAddress((void**)&xh,  g_x_hi);
    cudaGetSymbolAddress((void**)&xl,  g_x_lo);
    cudaGetSymbolAddress((void**)&wqh, g_wqkv_hi);
    cudaGetSymbolAddress((void**)&wql, g_wqkv_lo);
    cudaGetSymbolAddress((void**)&wph, g_wproj_hi);
    cudaGetSymbolAddress((void**)&qh,  g_qkv_hi);
    cudaGetSymbolAddress((void**)&ql,  g_qkv_lo);
    cudaGetSymbolAddress((void**)&ah,  g_att_hi);
    cudaGetSymbolAddress((void**)&al,  g_att_lo);

    cudaFuncSetAttribute((const void*)gemm_f16s<true, 3>,
                         cudaFuncAttributeMaxDynamicSharedMemorySize,
                         (int)sizeof(GemmSmem));
    cudaFuncSetAttribute((const void*)gemm_f16s<false, 2>,
                         cudaFuncAttributeMaxDynamicSharedMemorySize,
                         (int)sizeof(GemmSmem));
    cudaFuncSetAttribute((const void*)attn_mma,
                         cudaFuncAttributeMaxDynamicSharedMemorySize,
                         (int)sizeof(AttnSmem));

    // 0) split fp32 inputs into fp16 hi/lo planes
    {
        int n4 = M_TOT * DIM / 4;
        split_planes<<<(n4 + 255) / 256, 256>>>((const float4*)x,
                                                (uint2*)xh, (uint2*)xl, n4);
        n4 = QKV_N * DIM / 4;
        split_planes<<<(n4 + 255) / 256, 256>>>((const float4*)w_qkv,
                                                (uint2*)wqh, (uint2*)wql, n4);
        n4 = DIM * DIM / 4;
        split_planes<<<(n4 + 255) / 256, 256>>>((const float4*)w_proj,
                                                (uint2*)wph, nullptr, n4);
    }

    // 1) QKV projection (3-MMA split) -> split fp16 planes
    {
        dim3 grid(QKV_N / 256, M_TOT / 128);
        gemm_f16s<true, 3><<<grid, 256, sizeof(GemmSmem)>>>(
            xh, xl, wqh, wql, nullptr, qh, ql, nullptr, M_TOT, QKV_N, DIM);
    }

    // 2) Fused quadratic attention -> split fp16 planes
    {
        dim3 grid(SEQ / QB, NH, BB);
        attn_mma<<<grid, 256, sizeof(AttnSmem)>>>(qh, ql, alpha, beta, gamma,
                                                  ah, al);
    }

    // 3) Output projection + bias (2-MMA, B single fp16) -> fp32 out
    {
        dim3 grid(DIM / 256, M_TOT / 128);
        gemm_f16s<false, 2><<<grid, 256, sizeof(GemmSmem)>>>(
            ah, al, wph, nullptr, b_proj, nullptr, nullptr, out,
            M_TOT, DIM, DIM);
    }
}

// round 7
// speedup vs baseline: 1.2298x; 1.2298x over previous
#include <cuda_runtime.h>
#include <cuda_fp16.h>
#include <cstdint>
#include <cstddef>

#define DIM      768
#define NH       12
#define HD       64
#define BB       8
#define SEQ      1024
#define M_TOT    (BB * SEQ)          // 8192
#define QKV_N    (3 * DIM)           // 2304
#define ATT_SCALE 0.125f
#define QB       256                 // q rows per attention CTA

// ---------------------------------------------------------------------------
// Scratch planes (fp16 hi/lo splits). Device globals: allocation-free.
// ---------------------------------------------------------------------------
__device__ __half g_x_hi[(size_t)M_TOT * DIM];
__device__ __half g_x_lo[(size_t)M_TOT * DIM];
__device__ __half g_wqkv_hi[(size_t)QKV_N * DIM];
__device__ __half g_wproj_hi[(size_t)DIM * DIM];
__device__ __half g_qkv_hi[(size_t)M_TOT * QKV_N];
__device__ __half g_qkv_lo[(size_t)M_TOT * QKV_N];
__device__ __half g_att_hi[(size_t)M_TOT * DIM];
__device__ __half g_att_lo[(size_t)M_TOT * DIM];

// ---------------------------------------------------------------------------
// Helpers
// ---------------------------------------------------------------------------
__device__ __forceinline__ uint32_t sptr(const void* p) {
    return (uint32_t)__cvta_generic_to_shared(p);
}
__device__ __forceinline__ void cp16(void* dst, const void* src) {
    asm volatile("cp.async.cg.shared.global [%0], [%1], 16;"
                 :: "r"(sptr(dst)), "l"(src));
}
__device__ __forceinline__ void cp_commit() {
    asm volatile("cp.async.commit_group;");
}
template<int N>
__device__ __forceinline__ void cp_wait() {
    asm volatile("cp.async.wait_group %0;" :: "n"(N));
}
__device__ __forceinline__ void ldsm4(uint32_t r[4], uint32_t a) {
    asm volatile("ldmatrix.sync.aligned.m8n8.x4.shared.b16 {%0,%1,%2,%3}, [%4];"
                 : "=r"(r[0]), "=r"(r[1]), "=r"(r[2]), "=r"(r[3]) : "r"(a));
}
__device__ __forceinline__ void ldsm4t(uint32_t r[4], uint32_t a) {
    asm volatile("ldmatrix.sync.aligned.m8n8.x4.trans.shared.b16 {%0,%1,%2,%3}, [%4];"
                 : "=r"(r[0]), "=r"(r[1]), "=r"(r[2]), "=r"(r[3]) : "r"(a));
}
__device__ __forceinline__ void mma_f16(float c[4], const uint32_t a[4],
                                        uint32_t b0, uint32_t b1) {
    asm volatile(
        "mma.sync.aligned.m16n8k16.row.col.f32.f16.f16.f32 "
        "{%0,%1,%2,%3},{%4,%5,%6,%7},{%8,%9},{%0,%1,%2,%3};"
        : "+f"(c[0]), "+f"(c[1]), "+f"(c[2]), "+f"(c[3])
        : "r"(a[0]), "r"(a[1]), "r"(a[2]), "r"(a[3]), "r"(b0), "r"(b1));
}
__device__ __forceinline__ uint32_t pack_h(float a, float b) {
    __half2 t = __floats2half2_rn(a, b);
    return *reinterpret_cast<uint32_t*>(&t);
}
__device__ __forceinline__ void split_pair_h(float x, float y,
                                             uint32_t& hi, uint32_t& lo) {
    __half hx = __float2half_rn(x), hy = __float2half_rn(y);
    hi = (uint32_t)__half_as_ushort(hx) | ((uint32_t)__half_as_ushort(hy) << 16);
    lo = pack_h(x - __half2float(hx), y - __half2float(hy));
}

// ---------------------------------------------------------------------------
// fp32 -> fp16 hi/lo plane conversion
// ---------------------------------------------------------------------------
__global__ void split_planes(const float4* __restrict__ in,
                             uint2* __restrict__ hi, uint2* __restrict__ lo,
                             int n4) {
    int i = blockIdx.x * blockDim.x + threadIdx.x;
    if (i >= n4) return;
    float4 v = in[i];
    uint32_t h0, l0, h1, l1;
    split_pair_h(v.x, v.y, h0, l0);
    split_pair_h(v.z, v.w, h1, l1);
    hi[i] = make_uint2(h0, h1);
    if (lo) lo[i] = make_uint2(l0, l1);
}

// ---------------------------------------------------------------------------
// Split-fp16 tensor-core GEMM with cp.async 2-stage pipeline.
// C[M,N] = A[M,K] * B[N,K]^T. 128x128 CTA tile, BK=32, 8 warps (2m x 4n).
// NMMA=3: ah*bh + ah*bl + al*bh (exact to ~2^-22)
// NMMA=2: ah*bh + al*bh        (B single fp16, ~2e-4)
// ---------------------------------------------------------------------------
struct GemmSmem {
    __half Ah[2][128][40], Al[2][128][40];
    __half Bh[2][128][40], Bl[2][128][40];
};
extern __shared__ __align__(1024) char smem_raw[];

template<int NMMA>
__device__ __forceinline__ void gemm_load_stage(
    GemmSmem& s, int st,
    const __half* __restrict__ Ah_g, const __half* __restrict__ Al_g,
    const __half* __restrict__ Bh_g, const __half* __restrict__ Bl_g,
    int row0, int col0, int K, int k0, int tid)
{
#pragma unroll
    for (int l = 0; l < 2; l++) {
        int idx = tid + 256 * l;        // 0..511
        int r = idx >> 2, p = idx & 3;  // row, 16B slot
        cp16(&s.Ah[st][r][p * 8], &Ah_g[(size_t)(row0 + r) * K + k0 + p * 8]);
        cp16(&s.Al[st][r][p * 8], &Al_g[(size_t)(row0 + r) * K + k0 + p * 8]);
        cp16(&s.Bh[st][r][p * 8], &Bh_g[(size_t)(col0 + r) * K + k0 + p * 8]);
        if (NMMA == 3)
            cp16(&s.Bl[st][r][p * 8], &Bl_g[(size_t)(col0 + r) * K + k0 + p * 8]);
    }
}

template<bool SPLIT_OUT, int NMMA>
__global__ void __launch_bounds__(256, 2)
gemm_f16s(const __half* __restrict__ Ah_g,
          const __half* __restrict__ Al_g,
          const __half* __restrict__ Bh_g,
          const __half* __restrict__ Bl_g,
          const float* __restrict__ bias,
          __half* __restrict__ Ch,
          __half* __restrict__ Cl,
          float* __restrict__ Cf,
          int M, int N, int K)
{
    GemmSmem& s = *reinterpret_cast<GemmSmem*>(smem_raw);

    const int tid  = threadIdx.x;
    const int lane = tid & 31;
    const int w    = tid >> 5;
    const int wm   = w & 1;
    const int wn   = w >> 1;
    const int row0 = blockIdx.y * 128;
    const int col0 = blockIdx.x * 128;

    float acc[4][4][4];
#pragma unroll
    for (int a = 0; a < 4; a++)
#pragma unroll
        for (int b = 0; b < 4; b++)
#pragma unroll
            for (int c = 0; c < 4; c++) acc[a][b][c] = 0.f;

    const int nk = K / 32;
    gemm_load_stage<NMMA>(s, 0, Ah_g, Al_g, Bh_g, Bl_g, row0, col0, K, 0, tid);
    cp_commit();

    for (int i = 0; i < nk; i++) {
        const int st = i & 1;
        if (i + 1 < nk) {
            gemm_load_stage<NMMA>(s, st ^ 1, Ah_g, Al_g, Bh_g, Bl_g,
                                  row0, col0, K, (i + 1) * 32, tid);
            cp_commit();
            cp_wait<1>();
        } else {
            cp_wait<0>();
        }
        __syncthreads();

#pragma unroll
        for (int kk = 0; kk < 32; kk += 16) {
            uint32_t ah[4][4], al[4][4];
#pragma unroll
            for (int mt = 0; mt < 4; mt++) {
                int r = 64 * wm + 16 * mt + (lane & 15);
                int c = kk + (lane >> 4) * 8;
                ldsm4(ah[mt], sptr(&s.Ah[st][r][c]));
                ldsm4(al[mt], sptr(&s.Al[st][r][c]));
            }
#pragma unroll
            for (int np = 0; np < 2; np++) {
                uint32_t bh[4], bl[4];
                int r = 32 * wn + 16 * np + (lane & 7) + (lane >> 4) * 8;
                int c = kk + ((lane >> 3) & 1) * 8;
                ldsm4(bh, sptr(&s.Bh[st][r][c]));
                if (NMMA == 3) ldsm4(bl, sptr(&s.Bl[st][r][c]));
#pragma unroll
                for (int mt = 0; mt < 4; mt++) {
#pragma unroll
                    for (int h2 = 0; h2 < 2; h2++) {
                        float* cc = acc[mt][2 * np + h2];
                        mma_f16(cc, ah[mt], bh[2 * h2], bh[2 * h2 + 1]);
                        if (NMMA == 3)
                            mma_f16(cc, ah[mt], bl[2 * h2], bl[2 * h2 + 1]);
                        mma_f16(cc, al[mt], bh[2 * h2], bh[2 * h2 + 1]);
                    }
                }
            }
        }
        __syncthreads();
    }

    // Epilogue
#pragma unroll
    for (int mt = 0; mt < 4; mt++) {
#pragma unroll
        for (int nt = 0; nt < 4; nt++) {
            int gr = row0 + 64 * wm + 16 * mt + (lane >> 2);
            int gc = col0 + 32 * wn + 8 * nt + 2 * (lane & 3);
            const float* cc = acc[mt][nt];
            if (SPLIT_OUT) {
                uint32_t h, l;
                split_pair_h(cc[0], cc[1], h, l);
                *reinterpret_cast<uint32_t*>(&Ch[(size_t)gr * N + gc]) = h;
                *reinterpret_cast<uint32_t*>(&Cl[(size_t)gr * N + gc]) = l;
                split_pair_h(cc[2], cc[3], h, l);
                *reinterpret_cast<uint32_t*>(&Ch[(size_t)(gr + 8) * N + gc]) = h;
                *reinterpret_cast<uint32_t*>(&Cl[(size_t)(gr + 8) * N + gc]) = l;
            } else {
                float b0 = bias[gc], b1 = bias[gc + 1];
                *reinterpret_cast<float2*>(&Cf[(size_t)gr * N + gc]) =
                    make_float2(cc[0] + b0, cc[1] + b1);
                *reinterpret_cast<float2*>(&Cf[(size_t)(gr + 8) * N + gc]) =
                    make_float2(cc[2] + b0, cc[3] + b1);
            }
        }
    }
}

// ---------------------------------------------------------------------------
// Fused quadratic-ReLU attention (R5 config).
// CTA = 256 q-rows x (head, batch). 8 warps; warp w owns rows 32w..32w+31.
// S = QK^T 3-MMA split (exact); P,V single fp16 (1 MMA) for P*V.
// ---------------------------------------------------------------------------
struct AttnSmem {
    __half Kh[2][128][72], Kl[2][128][72], Vh[2][128][72];
};

__device__ __forceinline__ void load_tile72_async(
    __half (*dst)[72], const __half* __restrict__ src, int tid)
{
#pragma unroll
    for (int l = 0; l < 4; l++) {
        int idx = tid + 256 * l;
        int r = idx >> 3, p = idx & 7;
        cp16(&dst[r][p * 8], &src[(size_t)r * QKV_N + p * 8]);
    }
}

__global__ void __launch_bounds__(256, 1)
attn_mma(const __half* __restrict__ qkv_hi,
         const __half* __restrict__ qkv_lo,
         const float* __restrict__ alpha,
         const float* __restrict__ beta,
         const float* __restrict__ gamma,
         __half* __restrict__ att_hi,
         __half* __restrict__ att_lo)
{
    AttnSmem& s = *reinterpret_cast<AttnSmem*>(smem_raw);
    const int tid  = threadIdx.x;
    const int lane = tid & 31;
    const int w    = tid >> 5;
    const int qt   = blockIdx.x;
    const int h    = blockIdx.y;
    const int b    = blockIdx.z;
    const int q0   = qt * QB;

    const float av = alpha[h], bv = beta[h], gv = gamma[h];
    const size_t base = (size_t)(b * SEQ) * QKV_N + h * HD;

    load_tile72_async(s.Kh[0], qkv_hi + base + DIM,     tid);
    load_tile72_async(s.Kl[0], qkv_lo + base + DIM,     tid);
    load_tile72_async(s.Vh[0], qkv_hi + base + 2 * DIM, tid);
    cp_commit();

    uint32_t qh[2][4][4], ql[2][4][4];
    {
        const int rb = b * SEQ + q0 + 32 * w + (lane >> 2);
        const int cb = h * HD + 2 * (lane & 3);
#pragma unroll
        for (int rg = 0; rg < 2; rg++) {
#pragma unroll
            for (int kc = 0; kc < 4; kc++) {
                size_t o00 = (size_t)(rb + 16 * rg) * QKV_N + cb + 16 * kc;
                size_t o10 = o00 + 8 * QKV_N;
                qh[rg][kc][0] = *reinterpret_cast<const uint32_t*>(&qkv_hi[o00]);
                qh[rg][kc][1] = *reinterpret_cast<const uint32_t*>(&qkv_hi[o10]);
                qh[rg][kc][2] = *reinterpret_cast<const uint32_t*>(&qkv_hi[o00 + 8]);
                qh[rg][kc][3] = *reinterpret_cast<const uint32_t*>(&qkv_hi[o10 + 8]);
                ql[rg][kc][0] = *reinterpret_cast<const uint32_t*>(&qkv_lo[o00]);
                ql[rg][kc][1] = *reinterpret_cast<const uint32_t*>(&qkv_lo[o10]);
                ql[rg][kc][2] = *reinterpret_cast<const uint32_t*>(&qkv_lo[o00 + 8]);
                ql[rg][kc][3] = *reinterpret_cast<const uint32_t*>(&qkv_lo[o10 + 8]);
            }
        }
    }

    float O[2][8][4];
#pragma unroll
    for (int rg = 0; rg < 2; rg++)
#pragma unroll
        for (int j = 0; j < 8; j++)
#pragma unroll
            for (int q = 0; q < 4; q++) O[rg][j][q] = 0.f;
    float rs[2][2] = {{0.f, 0.f}, {0.f, 0.f}};

    for (int kt = 0; kt < SEQ / 128; kt++) {
        const int st = kt & 1;
        if (kt + 1 < SEQ / 128) {
            const size_t koff = base + (size_t)((kt + 1) * 128) * QKV_N;
            load_tile72_async(s.Kh[st ^ 1], qkv_hi + koff + DIM,     tid);
            load_tile72_async(s.Kl[st ^ 1], qkv_lo + koff + DIM,     tid);
            load_tile72_async(s.Vh[st ^ 1], qkv_hi + koff + 2 * DIM, tid);
            cp_commit();
            cp_wait<1>();
        } else {
            cp_wait<0>();
        }
        __syncthreads();

#pragma unroll
        for (int rg = 0; rg < 2; rg++) {
            float S[16][4];
#pragma unroll
            for (int j = 0; j < 16; j++)
#pragma unroll
                for (int q = 0; q < 4; q++) S[j][q] = 0.f;

#pragma unroll
            for (int kc = 0; kc < 4; kc++) {
#pragma unroll
                for (int np = 0; np < 8; np++) {
                    uint32_t kh[4], kl[4];
                    int r = 16 * np + (lane & 7) + (lane >> 4) * 8;
                    int c = 16 * kc + ((lane >> 3) & 1) * 8;
                    ldsm4(kh, sptr(&s.Kh[st][r][c]));
                    ldsm4(kl, sptr(&s.Kl[st][r][c]));
                    mma_f16(S[2 * np + 0], qh[rg][kc], kh[0], kh[1]);
                    mma_f16(S[2 * np + 0], qh[rg][kc], kl[0], kl[1]);
                    mma_f16(S[2 * np + 0], ql[rg][kc], kh[0], kh[1]);
                    mma_f16(S[2 * np + 1], qh[rg][kc], kh[2], kh[3]);
                    mma_f16(S[2 * np + 1], qh[rg][kc], kl[2], kl[3]);
                    mma_f16(S[2 * np + 1], ql[rg][kc], kh[2], kh[3]);
                }
            }

#pragma unroll
            for (int j = 0; j < 16; j++) {
#pragma unroll
                for (int q = 0; q < 4; q++) {
                    float z = S[j][q] * ATT_SCALE;
                    float p = fmaf(fmaf(av, z, bv), z, gv);
                    S[j][q] = fmaxf(p, 0.f);
                }
                rs[rg][0] += S[j][0] + S[j][1];
                rs[rg][1] += S[j][2] + S[j][3];
            }

#pragma unroll
            for (int c8 = 0; c8 < 8; c8++) {
                uint32_t ph[4];
                ph[0] = pack_h(S[2 * c8][0],     S[2 * c8][1]);
                ph[1] = pack_h(S[2 * c8][2],     S[2 * c8][3]);
                ph[2] = pack_h(S[2 * c8 + 1][0], S[2 * c8 + 1][1]);
                ph[3] = pack_h(S[2 * c8 + 1][2], S[2 * c8 + 1][3]);
#pragma unroll
                for (int ep = 0; ep < 4; ep++) {
                    uint32_t vh[4];
                    int r = 16 * c8 + (lane & 7) + ((lane >> 3) & 1) * 8;
                    int c = 16 * ep + (lane >> 4) * 8;
                    ldsm4t(vh, sptr(&s.Vh[st][r][c]));
                    mma_f16(O[rg][2 * ep + 0], ph, vh[0], vh[1]);
                    mma_f16(O[rg][2 * ep + 1], ph, vh[2], vh[3]);
                }
            }
        }
        __syncthreads();
    }

#pragma unroll
    for (int rg = 0; rg < 2; rg++) {
        float r0 = rs[rg][0], r1 = rs[rg][1];
        r0 += __shfl_xor_sync(0xffffffffu, r0, 1);
        r0 += __shfl_xor_sync(0xffffffffu, r0, 2);
        r1 += __shfl_xor_sync(0xffffffffu, r1, 1);
        r1 += __shfl_xor_sync(0xffffffffu, r1, 2);
        const float inv0 = 1.f / (r0 + 1e-6f);
        const float inv1 = 1.f / (r1 + 1e-6f);

        const int row = b * SEQ + q0 + 32 * w + 16 * rg + (lane >> 2);
#pragma unroll
        for (int j = 0; j < 8; j++) {
            int ce = h * HD + 8 * j + 2 * (lane & 3);
            uint32_t hh, ll;
            split_pair_h(O[rg][j][0] * inv0, O[rg][j][1] * inv0, hh, ll);
            *reinterpret_cast<uint32_t*>(&att_hi[(size_t)row * DIM + ce]) = hh;
            *reinterpret_cast<uint32_t*>(&att_lo[(size_t)row * DIM + ce]) = ll;
            split_pair_h(O[rg][j][2] * inv1, O[rg][j][3] * inv1, hh, ll);
            *reinterpret_cast<uint32_t*>(&att_hi[(size_t)(row + 8) * DIM + ce]) = hh;
            *reinterpret_cast<uint32_t*>(&att_lo[(size_t)(row + 8) * DIM + ce]) = ll;
        }
    }
}

// ---------------------------------------------------------------------------
// Launch
// ---------------------------------------------------------------------------
extern "C" void kernel_launch(void* const* d_in, const int* in_sizes, int n_in,
                              void* d_out, int out_size)
{
    const float* x      = (const float*)d_in[0];
    const float* w_qkv  = (const float*)d_in[1];
    const float* w_proj = (const float*)d_in[2];
    const float* b_proj = (const float*)d_in[3];
    const float* alpha  = (const float*)d_in[4];
    const float* beta   = (const float*)d_in[5];
    const float* gamma  = (const float*)d_in[6];
    float* out = (float*)d_out;

    __half *xh, *xl, *wqh, *wph, *qh, *ql, *ah, *al;
    cudaGetSymbolAddress((void**)&xh,  g_x_hi);
    cudaGetSymbolAddress((void**)&xl,  g_x_lo);
    cudaGetSymbolAddress((void**)&wqh, g_wqkv_hi);
    cudaGetSymbolAddress((void**)&wph, g_wproj_hi);
    cudaGetSymbolAddress((void**)&qh,  g_qkv_hi);
    cudaGetSymbolAddress((void**)&ql,  g_qkv_lo);
    cudaGetSymbolAddress((void**)&ah,  g_att_hi);
    cudaGetSymbolAddress((void**)&al,  g_att_lo);

    cudaFuncSetAttribute((const void*)gemm_f16s<true, 2>,
                         cudaFuncAttributeMaxDynamicSharedMemorySize,
                         (int)sizeof(GemmSmem));
    cudaFuncSetAttribute((const void*)gemm_f16s<false, 2>,
                         cudaFuncAttributeMaxDynamicSharedMemorySize,
                         (int)sizeof(GemmSmem));
    cudaFuncSetAttribute((const void*)attn_mma,
                         cudaFuncAttributeMaxDynamicSharedMemorySize,
                         (int)sizeof(AttnSmem));

    // 0) split fp32 inputs into fp16 hi/lo planes
    {
        int n4 = M_TOT * DIM / 4;
        split_planes<<<(n4 + 255) / 256, 256>>>((const float4*)x,
                                                (uint2*)xh, (uint2*)xl, n4);
        n4 = QKV_N * DIM / 4;
        split_planes<<<(n4 + 255) / 256, 256>>>((const float4*)w_qkv,
                                                (uint2*)wqh, nullptr, n4);
        n4 = DIM * DIM / 4;
        split_planes<<<(n4 + 255) / 256, 256>>>((const float4*)w_proj,
                                                (uint2*)wph, nullptr, n4);
    }

    // 1) QKV projection (2-MMA: x split, w single fp16) -> split fp16 planes
    {
        dim3 grid(QKV_N / 128, M_TOT / 128);
        gemm_f16s<true, 2><<<grid, 256, sizeof(GemmSmem)>>>(
            xh, xl, wqh, nullptr, nullptr, qh, ql, nullptr, M_TOT, QKV_N, DIM);
    }

    // 2) Fused quadratic attention -> split fp16 planes
    {
        dim3 grid(SEQ / QB, NH, BB);
        attn_mma<<<grid, 256, sizeof(AttnSmem)>>>(qh, ql, alpha, beta, gamma,
                                                  ah, al);
    }

    // 3) Output projection + bias (2-MMA, B single fp16) -> fp32 out
    {
        dim3 grid(DIM / 128, M_TOT / 128);
        gemm_f16s<false, 2><<<grid, 256, sizeof(GemmSmem)>>>(
            ah, al, wph, nullptr, b_proj, nullptr, nullptr, out,
            M_TOT, DIM, DIM);
    }
}

// round 8
// speedup vs baseline: 1.5949x; 1.2969x over previous
#include <cuda_runtime.h>
#include <cuda_fp16.h>
#include <cstdint>
#include <cstddef>

#define DIM      768
#define NH       12
#define HD       64
#define BB       8
#define SEQ      1024
#define M_TOT    (BB * SEQ)          // 8192
#define QKV_N    (3 * DIM)           // 2304
#define ATT_SCALE 0.125f
#define QB       256                 // q rows per attention CTA

// ---------------------------------------------------------------------------
// Scratch planes. Device globals: allocation-free.
// ---------------------------------------------------------------------------
__device__ __half g_x_hi[(size_t)M_TOT * DIM];
__device__ __half g_wqkv_hi[(size_t)QKV_N * DIM];
__device__ __half g_wproj_hi[(size_t)DIM * DIM];
__device__ __half g_qkv_hi[(size_t)M_TOT * QKV_N];   // output split hi
__device__ __half g_qkv_lo[(size_t)M_TOT * QKV_N];   // output split lo
__device__ __half g_att_hi[(size_t)M_TOT * DIM];

// ---------------------------------------------------------------------------
// Helpers
// ---------------------------------------------------------------------------
__device__ __forceinline__ uint32_t sptr(const void* p) {
    return (uint32_t)__cvta_generic_to_shared(p);
}
__device__ __forceinline__ void cp16(void* dst, const void* src) {
    asm volatile("cp.async.cg.shared.global [%0], [%1], 16;"
                 :: "r"(sptr(dst)), "l"(src));
}
__device__ __forceinline__ void cp_commit() {
    asm volatile("cp.async.commit_group;");
}
template<int N>
__device__ __forceinline__ void cp_wait() {
    asm volatile("cp.async.wait_group %0;" :: "n"(N));
}
__device__ __forceinline__ void ldsm4(uint32_t r[4], uint32_t a) {
    asm volatile("ldmatrix.sync.aligned.m8n8.x4.shared.b16 {%0,%1,%2,%3}, [%4];"
                 : "=r"(r[0]), "=r"(r[1]), "=r"(r[2]), "=r"(r[3]) : "r"(a));
}
__device__ __forceinline__ void ldsm4t(uint32_t r[4], uint32_t a) {
    asm volatile("ldmatrix.sync.aligned.m8n8.x4.trans.shared.b16 {%0,%1,%2,%3}, [%4];"
                 : "=r"(r[0]), "=r"(r[1]), "=r"(r[2]), "=r"(r[3]) : "r"(a));
}
__device__ __forceinline__ void mma_f16(float c[4], const uint32_t a[4],
                                        uint32_t b0, uint32_t b1) {
    asm volatile(
        "mma.sync.aligned.m16n8k16.row.col.f32.f16.f16.f32 "
        "{%0,%1,%2,%3},{%4,%5,%6,%7},{%8,%9},{%0,%1,%2,%3};"
        : "+f"(c[0]), "+f"(c[1]), "+f"(c[2]), "+f"(c[3])
        : "r"(a[0]), "r"(a[1]), "r"(a[2]), "r"(a[3]), "r"(b0), "r"(b1));
}
__device__ __forceinline__ uint32_t pack_h(float a, float b) {
    __half2 t = __floats2half2_rn(a, b);
    return *reinterpret_cast<uint32_t*>(&t);
}
__device__ __forceinline__ void split_pair_h(float x, float y,
                                             uint32_t& hi, uint32_t& lo) {
    __half hx = __float2half_rn(x), hy = __float2half_rn(y);
    hi = (uint32_t)__half_as_ushort(hx) | ((uint32_t)__half_as_ushort(hy) << 16);
    lo = pack_h(x - __half2float(hx), y - __half2float(hy));
}

// ---------------------------------------------------------------------------
// fp32 -> fp16 plane conversion (hi only, or hi+lo)
// ---------------------------------------------------------------------------
__global__ void split_planes(const float4* __restrict__ in,
                             uint2* __restrict__ hi, uint2* __restrict__ lo,
                             int n4) {
    int i = blockIdx.x * blockDim.x + threadIdx.x;
    if (i >= n4) return;
    float4 v = in[i];
    uint32_t h0, l0, h1, l1;
    split_pair_h(v.x, v.y, h0, l0);
    split_pair_h(v.z, v.w, h1, l1);
    hi[i] = make_uint2(h0, h1);
    if (lo) lo[i] = make_uint2(l0, l1);
}

// ---------------------------------------------------------------------------
// fp16 tensor-core GEMM with cp.async 2-stage pipeline.
// C[M,N] = A[M,K] * B[N,K]^T. 128x128 CTA tile, BK=32, 8 warps (2m x 4n).
// NMMA=1: ah*bh. NMMA=2: +al*bh. NMMA=3: +ah*bl.
// Struct ordered so NMMA=1 only needs the first 40KB.
// ---------------------------------------------------------------------------
struct GemmSmem {
    __half Ah[2][128][40], Bh[2][128][40];
    __half Al[2][128][40], Bl[2][128][40];
};
#define GEMM_SMEM_1 (4 * 128 * 40 * 2)     // Ah+Bh, both stages: 40960 B
extern __shared__ __align__(1024) char smem_raw[];

template<int NMMA>
__device__ __forceinline__ void gemm_load_stage(
    GemmSmem& s, int st,
    const __half* __restrict__ Ah_g, const __half* __restrict__ Al_g,
    const __half* __restrict__ Bh_g, const __half* __restrict__ Bl_g,
    int row0, int col0, int K, int k0, int tid)
{
#pragma unroll
    for (int l = 0; l < 2; l++) {
        int idx = tid + 256 * l;        // 0..511
        int r = idx >> 2, p = idx & 3;  // row, 16B slot
        cp16(&s.Ah[st][r][p * 8], &Ah_g[(size_t)(row0 + r) * K + k0 + p * 8]);
        cp16(&s.Bh[st][r][p * 8], &Bh_g[(size_t)(col0 + r) * K + k0 + p * 8]);
        if (NMMA >= 2)
            cp16(&s.Al[st][r][p * 8], &Al_g[(size_t)(row0 + r) * K + k0 + p * 8]);
        if (NMMA == 3)
            cp16(&s.Bl[st][r][p * 8], &Bl_g[(size_t)(col0 + r) * K + k0 + p * 8]);
    }
}

template<bool SPLIT_OUT, int NMMA>
__global__ void __launch_bounds__(256, 2)
gemm_f16s(const __half* __restrict__ Ah_g,
          const __half* __restrict__ Al_g,
          const __half* __restrict__ Bh_g,
          const __half* __restrict__ Bl_g,
          const float* __restrict__ bias,
          __half* __restrict__ Ch,
          __half* __restrict__ Cl,
          float* __restrict__ Cf,
          int M, int N, int K)
{
    GemmSmem& s = *reinterpret_cast<GemmSmem*>(smem_raw);

    const int tid  = threadIdx.x;
    const int lane = tid & 31;
    const int w    = tid >> 5;
    const int wm   = w & 1;
    const int wn   = w >> 1;
    const int row0 = blockIdx.y * 128;
    const int col0 = blockIdx.x * 128;

    float acc[4][4][4];
#pragma unroll
    for (int a = 0; a < 4; a++)
#pragma unroll
        for (int b = 0; b < 4; b++)
#pragma unroll
            for (int c = 0; c < 4; c++) acc[a][b][c] = 0.f;

    const int nk = K / 32;
    gemm_load_stage<NMMA>(s, 0, Ah_g, Al_g, Bh_g, Bl_g, row0, col0, K, 0, tid);
    cp_commit();

    for (int i = 0; i < nk; i++) {
        const int st = i & 1;
        if (i + 1 < nk) {
            gemm_load_stage<NMMA>(s, st ^ 1, Ah_g, Al_g, Bh_g, Bl_g,
                                  row0, col0, K, (i + 1) * 32, tid);
            cp_commit();
            cp_wait<1>();
        } else {
            cp_wait<0>();
        }
        __syncthreads();

#pragma unroll
        for (int kk = 0; kk < 32; kk += 16) {
            uint32_t ah[4][4], al[4][4];
#pragma unroll
            for (int mt = 0; mt < 4; mt++) {
                int r = 64 * wm + 16 * mt + (lane & 15);
                int c = kk + (lane >> 4) * 8;
                ldsm4(ah[mt], sptr(&s.Ah[st][r][c]));
                if (NMMA >= 2) ldsm4(al[mt], sptr(&s.Al[st][r][c]));
            }
#pragma unroll
            for (int np = 0; np < 2; np++) {
                uint32_t bh[4], bl[4];
                int r = 32 * wn + 16 * np + (lane & 7) + (lane >> 4) * 8;
                int c = kk + ((lane >> 3) & 1) * 8;
                ldsm4(bh, sptr(&s.Bh[st][r][c]));
                if (NMMA == 3) ldsm4(bl, sptr(&s.Bl[st][r][c]));
#pragma unroll
                for (int mt = 0; mt < 4; mt++) {
#pragma unroll
                    for (int h2 = 0; h2 < 2; h2++) {
                        float* cc = acc[mt][2 * np + h2];
                        mma_f16(cc, ah[mt], bh[2 * h2], bh[2 * h2 + 1]);
                        if (NMMA == 3)
                            mma_f16(cc, ah[mt], bl[2 * h2], bl[2 * h2 + 1]);
                        if (NMMA >= 2)
                            mma_f16(cc, al[mt], bh[2 * h2], bh[2 * h2 + 1]);
                    }
                }
            }
        }
        __syncthreads();
    }

    // Epilogue
#pragma unroll
    for (int mt = 0; mt < 4; mt++) {
#pragma unroll
        for (int nt = 0; nt < 4; nt++) {
            int gr = row0 + 64 * wm + 16 * mt + (lane >> 2);
            int gc = col0 + 32 * wn + 8 * nt + 2 * (lane & 3);
            const float* cc = acc[mt][nt];
            if (SPLIT_OUT) {
                uint32_t h, l;
                split_pair_h(cc[0], cc[1], h, l);
                *reinterpret_cast<uint32_t*>(&Ch[(size_t)gr * N + gc]) = h;
                *reinterpret_cast<uint32_t*>(&Cl[(size_t)gr * N + gc]) = l;
                split_pair_h(cc[2], cc[3], h, l);
                *reinterpret_cast<uint32_t*>(&Ch[(size_t)(gr + 8) * N + gc]) = h;
                *reinterpret_cast<uint32_t*>(&Cl[(size_t)(gr + 8) * N + gc]) = l;
            } else {
                float b0 = bias[gc], b1 = bias[gc + 1];
                *reinterpret_cast<float2*>(&Cf[(size_t)gr * N + gc]) =
                    make_float2(cc[0] + b0, cc[1] + b1);
                *reinterpret_cast<float2*>(&Cf[(size_t)(gr + 8) * N + gc]) =
                    make_float2(cc[2] + b0, cc[3] + b1);
            }
        }
    }
}

// ---------------------------------------------------------------------------
// Fused quadratic-ReLU attention.
// CTA = 256 q-rows x (head, batch). 8 warps; warp w owns rows 32w..32w+31.
// S = QK^T 3-MMA split (exact vs f32 qkv); P,V single fp16 for P*V.
// Epilogue writes only hi plane (proj GEMM is single-plane A).
// ---------------------------------------------------------------------------
struct AttnSmem {
    __half Kh[2][128][72], Kl[2][128][72], Vh[2][128][72];
};

__device__ __forceinline__ void load_tile72_async(
    __half (*dst)[72], const __half* __restrict__ src, int tid)
{
#pragma unroll
    for (int l = 0; l < 4; l++) {
        int idx = tid + 256 * l;
        int r = idx >> 3, p = idx & 7;
        cp16(&dst[r][p * 8], &src[(size_t)r * QKV_N + p * 8]);
    }
}

__global__ void __launch_bounds__(256, 1)
attn_mma(const __half* __restrict__ qkv_hi,
         const __half* __restrict__ qkv_lo,
         const float* __restrict__ alpha,
         const float* __restrict__ beta,
         const float* __restrict__ gamma,
         __half* __restrict__ att_hi)
{
    AttnSmem& s = *reinterpret_cast<AttnSmem*>(smem_raw);
    const int tid  = threadIdx.x;
    const int lane = tid & 31;
    const int w    = tid >> 5;
    const int qt   = blockIdx.x;
    const int h    = blockIdx.y;
    const int b    = blockIdx.z;
    const int q0   = qt * QB;

    const float av = alpha[h], bv = beta[h], gv = gamma[h];
    const size_t base = (size_t)(b * SEQ) * QKV_N + h * HD;

    load_tile72_async(s.Kh[0], qkv_hi + base + DIM,     tid);
    load_tile72_async(s.Kl[0], qkv_lo + base + DIM,     tid);
    load_tile72_async(s.Vh[0], qkv_hi + base + 2 * DIM, tid);
    cp_commit();

    uint32_t qh[2][4][4], ql[2][4][4];
    {
        const int rb = b * SEQ + q0 + 32 * w + (lane >> 2);
        const int cb = h * HD + 2 * (lane & 3);
#pragma unroll
        for (int rg = 0; rg < 2; rg++) {
#pragma unroll
            for (int kc = 0; kc < 4; kc++) {
                size_t o00 = (size_t)(rb + 16 * rg) * QKV_N + cb + 16 * kc;
                size_t o10 = o00 + 8 * QKV_N;
                qh[rg][kc][0] = *reinterpret_cast<const uint32_t*>(&qkv_hi[o00]);
                qh[rg][kc][1] = *reinterpret_cast<const uint32_t*>(&qkv_hi[o10]);
                qh[rg][kc][2] = *reinterpret_cast<const uint32_t*>(&qkv_hi[o00 + 8]);
                qh[rg][kc][3] = *reinterpret_cast<const uint32_t*>(&qkv_hi[o10 + 8]);
                ql[rg][kc][0] = *reinterpret_cast<const uint32_t*>(&qkv_lo[o00]);
                ql[rg][kc][1] = *reinterpret_cast<const uint32_t*>(&qkv_lo[o10]);
                ql[rg][kc][2] = *reinterpret_cast<const uint32_t*>(&qkv_lo[o00 + 8]);
                ql[rg][kc][3] = *reinterpret_cast<const uint32_t*>(&qkv_lo[o10 + 8]);
            }
        }
    }

    float O[2][8][4];
#pragma unroll
    for (int rg = 0; rg < 2; rg++)
#pragma unroll
        for (int j = 0; j < 8; j++)
#pragma unroll
            for (int q = 0; q < 4; q++) O[rg][j][q] = 0.f;
    float rs[2][2] = {{0.f, 0.f}, {0.f, 0.f}};

    for (int kt = 0; kt < SEQ / 128; kt++) {
        const int st = kt & 1;
        if (kt + 1 < SEQ / 128) {
            const size_t koff = base + (size_t)((kt + 1) * 128) * QKV_N;
            load_tile72_async(s.Kh[st ^ 1], qkv_hi + koff + DIM,     tid);
            load_tile72_async(s.Kl[st ^ 1], qkv_lo + koff + DIM,     tid);
            load_tile72_async(s.Vh[st ^ 1], qkv_hi + koff + 2 * DIM, tid);
            cp_commit();
            cp_wait<1>();
        } else {
            cp_wait<0>();
        }
        __syncthreads();

#pragma unroll
        for (int rg = 0; rg < 2; rg++) {
            float S[16][4];
#pragma unroll
            for (int j = 0; j < 16; j++)
#pragma unroll
                for (int q = 0; q < 4; q++) S[j][q] = 0.f;

#pragma unroll
            for (int kc = 0; kc < 4; kc++) {
#pragma unroll
                for (int np = 0; np < 8; np++) {
                    uint32_t kh[4], kl[4];
                    int r = 16 * np + (lane & 7) + (lane >> 4) * 8;
                    int c = 16 * kc + ((lane >> 3) & 1) * 8;
                    ldsm4(kh, sptr(&s.Kh[st][r][c]));
                    ldsm4(kl, sptr(&s.Kl[st][r][c]));
                    mma_f16(S[2 * np + 0], qh[rg][kc], kh[0], kh[1]);
                    mma_f16(S[2 * np + 0], qh[rg][kc], kl[0], kl[1]);
                    mma_f16(S[2 * np + 0], ql[rg][kc], kh[0], kh[1]);
                    mma_f16(S[2 * np + 1], qh[rg][kc], kh[2], kh[3]);
                    mma_f16(S[2 * np + 1], qh[rg][kc], kl[2], kl[3]);
                    mma_f16(S[2 * np + 1], ql[rg][kc], kh[2], kh[3]);
                }
            }

#pragma unroll
            for (int j = 0; j < 16; j++) {
#pragma unroll
                for (int q = 0; q < 4; q++) {
                    float z = S[j][q] * ATT_SCALE;
                    float p = fmaf(fmaf(av, z, bv), z, gv);
                    S[j][q] = fmaxf(p, 0.f);
                }
                rs[rg][0] += S[j][0] + S[j][1];
                rs[rg][1] += S[j][2] + S[j][3];
            }

#pragma unroll
            for (int c8 = 0; c8 < 8; c8++) {
                uint32_t ph[4];
                ph[0] = pack_h(S[2 * c8][0],     S[2 * c8][1]);
                ph[1] = pack_h(S[2 * c8][2],     S[2 * c8][3]);
                ph[2] = pack_h(S[2 * c8 + 1][0], S[2 * c8 + 1][1]);
                ph[3] = pack_h(S[2 * c8 + 1][2], S[2 * c8 + 1][3]);
#pragma unroll
                for (int ep = 0; ep < 4; ep++) {
                    uint32_t vh[4];
                    int r = 16 * c8 + (lane & 7) + ((lane >> 3) & 1) * 8;
                    int c = 16 * ep + (lane >> 4) * 8;
                    ldsm4t(vh, sptr(&s.Vh[st][r][c]));
                    mma_f16(O[rg][2 * ep + 0], ph, vh[0], vh[1]);
                    mma_f16(O[rg][2 * ep + 1], ph, vh[2], vh[3]);
                }
            }
        }
        __syncthreads();
    }

#pragma unroll
    for (int rg = 0; rg < 2; rg++) {
        float r0 = rs[rg][0], r1 = rs[rg][1];
        r0 += __shfl_xor_sync(0xffffffffu, r0, 1);
        r0 += __shfl_xor_sync(0xffffffffu, r0, 2);
        r1 += __shfl_xor_sync(0xffffffffu, r1, 1);
        r1 += __shfl_xor_sync(0xffffffffu, r1, 2);
        const float inv0 = 1.f / (r0 + 1e-6f);
        const float inv1 = 1.f / (r1 + 1e-6f);

        const int row = b * SEQ + q0 + 32 * w + 16 * rg + (lane >> 2);
#pragma unroll
        for (int j = 0; j < 8; j++) {
            int ce = h * HD + 8 * j + 2 * (lane & 3);
            *reinterpret_cast<uint32_t*>(&att_hi[(size_t)row * DIM + ce]) =
                pack_h(O[rg][j][0] * inv0, O[rg][j][1] * inv0);
            *reinterpret_cast<uint32_t*>(&att_hi[(size_t)(row + 8) * DIM + ce]) =
                pack_h(O[rg][j][2] * inv1, O[rg][j][3] * inv1);
        }
    }
}

// ---------------------------------------------------------------------------
// Launch
// ---------------------------------------------------------------------------
extern "C" void kernel_launch(void* const* d_in, const int* in_sizes, int n_in,
                              void* d_out, int out_size)
{
    const float* x      = (const float*)d_in[0];
    const float* w_qkv  = (const float*)d_in[1];
    const float* w_proj = (const float*)d_in[2];
    const float* b_proj = (const float*)d_in[3];
    const float* alpha  = (const float*)d_in[4];
    const float* beta   = (const float*)d_in[5];
    const float* gamma  = (const float*)d_in[6];
    float* out = (float*)d_out;

    __half *xh, *wqh, *wph, *qh, *ql, *ah;
    cudaGetSymbolAddress((void**)&xh,  g_x_hi);
    cudaGetSymbolAddress((void**)&wqh, g_wqkv_hi);
    cudaGetSymbolAddress((void**)&wph, g_wproj_hi);
    cudaGetSymbolAddress((void**)&qh,  g_qkv_hi);
    cudaGetSymbolAddress((void**)&ql,  g_qkv_lo);
    cudaGetSymbolAddress((void**)&ah,  g_att_hi);

    cudaFuncSetAttribute((const void*)gemm_f16s<true, 1>,
                         cudaFuncAttributeMaxDynamicSharedMemorySize,
                         GEMM_SMEM_1);
    cudaFuncSetAttribute((const void*)gemm_f16s<false, 1>,
                         cudaFuncAttributeMaxDynamicSharedMemorySize,
                         GEMM_SMEM_1);
    cudaFuncSetAttribute((const void*)attn_mma,
                         cudaFuncAttributeMaxDynamicSharedMemorySize,
                         (int)sizeof(AttnSmem));

    // 0) fp32 -> fp16 hi planes (no lo planes needed on inputs)
    {
        int n4 = M_TOT * DIM / 4;
        split_planes<<<(n4 + 255) / 256, 256>>>((const float4*)x,
                                                (uint2*)xh, nullptr, n4);
        n4 = QKV_N * DIM / 4;
        split_planes<<<(n4 + 255) / 256, 256>>>((const float4*)w_qkv,
                                                (uint2*)wqh, nullptr, n4);
        n4 = DIM * DIM / 4;
        split_planes<<<(n4 + 255) / 256, 256>>>((const float4*)w_proj,
                                                (uint2*)wph, nullptr, n4);
    }

    // 1) QKV projection (1 MMA: x single x w single) -> split output planes
    {
        dim3 grid(QKV_N / 128, M_TOT / 128);
        gemm_f16s<true, 1><<<grid, 256, GEMM_SMEM_1>>>(
            xh, nullptr, wqh, nullptr, nullptr, qh, ql, nullptr,
            M_TOT, QKV_N, DIM);
    }

    // 2) Fused quadratic attention -> att hi plane
    {
        dim3 grid(SEQ / QB, NH, BB);
        attn_mma<<<grid, 256, sizeof(AttnSmem)>>>(qh, ql, alpha, beta, gamma, ah);
    }

    // 3) Output projection + bias (1 MMA) -> fp32 out
    {
        dim3 grid(DIM / 128, M_TOT / 128);
        gemm_f16s<false, 1><<<grid, 256, GEMM_SMEM_1>>>(
            ah, nullptr, wph, nullptr, b_proj, nullptr, nullptr, out,
            M_TOT, DIM, DIM);
    }
}

// round 9
// speedup vs baseline: 2.3484x; 1.4724x over previous
#include <cuda_runtime.h>
#include <cuda_fp16.h>
#include <cstdint>
#include <cstddef>

#define DIM      768
#define NH       12
#define HD       64
#define BB       8
#define SEQ      1024
#define M_TOT    (BB * SEQ)          // 8192
#define QKV_N    (3 * DIM)           // 2304
#define ATT_SCALE 0.125f
#define QB       256                 // q rows per attention CTA

// ---------------------------------------------------------------------------
// Scratch planes. Device globals: allocation-free.
// ---------------------------------------------------------------------------
__device__ __half g_x_hi[(size_t)M_TOT * DIM];
__device__ __half g_wqkv_hi[(size_t)QKV_N * DIM];
__device__ __half g_wproj_hi[(size_t)DIM * DIM];
__device__ __half g_qkv_hi[(size_t)M_TOT * QKV_N];
__device__ __half g_att_hi[(size_t)M_TOT * DIM];

// ---------------------------------------------------------------------------
// Helpers
// ---------------------------------------------------------------------------
__device__ __forceinline__ uint32_t sptr(const void* p) {
    return (uint32_t)__cvta_generic_to_shared(p);
}
__device__ __forceinline__ void cp16(void* dst, const void* src) {
    asm volatile("cp.async.cg.shared.global [%0], [%1], 16;"
                 :: "r"(sptr(dst)), "l"(src));
}
__device__ __forceinline__ void cp_commit() {
    asm volatile("cp.async.commit_group;");
}
template<int N>
__device__ __forceinline__ void cp_wait() {
    asm volatile("cp.async.wait_group %0;" :: "n"(N));
}
__device__ __forceinline__ void ldsm4(uint32_t r[4], uint32_t a) {
    asm volatile("ldmatrix.sync.aligned.m8n8.x4.shared.b16 {%0,%1,%2,%3}, [%4];"
                 : "=r"(r[0]), "=r"(r[1]), "=r"(r[2]), "=r"(r[3]) : "r"(a));
}
__device__ __forceinline__ void ldsm4t(uint32_t r[4], uint32_t a) {
    asm volatile("ldmatrix.sync.aligned.m8n8.x4.trans.shared.b16 {%0,%1,%2,%3}, [%4];"
                 : "=r"(r[0]), "=r"(r[1]), "=r"(r[2]), "=r"(r[3]) : "r"(a));
}
__device__ __forceinline__ void mma_f16(float c[4], const uint32_t a[4],
                                        uint32_t b0, uint32_t b1) {
    asm volatile(
        "mma.sync.aligned.m16n8k16.row.col.f32.f16.f16.f32 "
        "{%0,%1,%2,%3},{%4,%5,%6,%7},{%8,%9},{%0,%1,%2,%3};"
        : "+f"(c[0]), "+f"(c[1]), "+f"(c[2]), "+f"(c[3])
        : "r"(a[0]), "r"(a[1]), "r"(a[2]), "r"(a[3]), "r"(b0), "r"(b1));
}
__device__ __forceinline__ uint32_t pack_h(float a, float b) {
    __half2 t = __floats2half2_rn(a, b);
    return *reinterpret_cast<uint32_t*>(&t);
}

// ---------------------------------------------------------------------------
// fp32 -> fp16 plane conversion (hi plane only)
// ---------------------------------------------------------------------------
__global__ void to_half_kernel(const float4* __restrict__ in,
                               uint2* __restrict__ hi, int n4) {
    int i = blockIdx.x * blockDim.x + threadIdx.x;
    if (i >= n4) return;
    float4 v = in[i];
    hi[i] = make_uint2(pack_h(v.x, v.y), pack_h(v.z, v.w));
}

// ---------------------------------------------------------------------------
// fp16 tensor-core GEMM, cp.async 2-stage, BK=64.
// C[M,N] = A[M,K] * B[N,K]^T. 128x128 CTA tile, 8 warps (2m x 4n).
// OUT=0: fp32 + bias. OUT=1: fp16 plane.
// ---------------------------------------------------------------------------
struct GemmSmem {
    __half Ah[2][128][72], Bh[2][128][72];
};
extern __shared__ __align__(1024) char smem_raw[];

__device__ __forceinline__ void gemm_load_stage(
    GemmSmem& s, int st,
    const __half* __restrict__ Ah_g, const __half* __restrict__ Bh_g,
    int row0, int col0, int K, int k0, int tid)
{
#pragma unroll
    for (int l = 0; l < 4; l++) {
        int idx = tid + 256 * l;        // 0..1023
        int r = idx >> 3, p = idx & 7;  // row, 16B slot (8 per 64-half row)
        cp16(&s.Ah[st][r][p * 8], &Ah_g[(size_t)(row0 + r) * K + k0 + p * 8]);
        cp16(&s.Bh[st][r][p * 8], &Bh_g[(size_t)(col0 + r) * K + k0 + p * 8]);
    }
}

template<int OUT>
__global__ void __launch_bounds__(256, 2)
gemm_f16(const __half* __restrict__ Ah_g,
         const __half* __restrict__ Bh_g,
         const float* __restrict__ bias,
         __half* __restrict__ Ch,
         float* __restrict__ Cf,
         int M, int N, int K)
{
    GemmSmem& s = *reinterpret_cast<GemmSmem*>(smem_raw);

    const int tid  = threadIdx.x;
    const int lane = tid & 31;
    const int w    = tid >> 5;
    const int wm   = w & 1;
    const int wn   = w >> 1;
    const int row0 = blockIdx.y * 128;
    const int col0 = blockIdx.x * 128;

    float acc[4][4][4];
#pragma unroll
    for (int a = 0; a < 4; a++)
#pragma unroll
        for (int b = 0; b < 4; b++)
#pragma unroll
            for (int c = 0; c < 4; c++) acc[a][b][c] = 0.f;

    const int nk = K / 64;
    gemm_load_stage(s, 0, Ah_g, Bh_g, row0, col0, K, 0, tid);
    cp_commit();

    for (int i = 0; i < nk; i++) {
        const int st = i & 1;
        if (i + 1 < nk) {
            gemm_load_stage(s, st ^ 1, Ah_g, Bh_g, row0, col0, K,
                            (i + 1) * 64, tid);
            cp_commit();
            cp_wait<1>();
        } else {
            cp_wait<0>();
        }
        __syncthreads();

#pragma unroll
        for (int kk = 0; kk < 64; kk += 16) {
            uint32_t ah[4][4];
#pragma unroll
            for (int mt = 0; mt < 4; mt++) {
                int r = 64 * wm + 16 * mt + (lane & 15);
                int c = kk + (lane >> 4) * 8;
                ldsm4(ah[mt], sptr(&s.Ah[st][r][c]));
            }
#pragma unroll
            for (int np = 0; np < 2; np++) {
                uint32_t bh[4];
                int r = 32 * wn + 16 * np + (lane & 7) + (lane >> 4) * 8;
                int c = kk + ((lane >> 3) & 1) * 8;
                ldsm4(bh, sptr(&s.Bh[st][r][c]));
#pragma unroll
                for (int mt = 0; mt < 4; mt++) {
                    mma_f16(acc[mt][2 * np + 0], ah[mt], bh[0], bh[1]);
                    mma_f16(acc[mt][2 * np + 1], ah[mt], bh[2], bh[3]);
                }
            }
        }
        __syncthreads();
    }

    // Epilogue
#pragma unroll
    for (int mt = 0; mt < 4; mt++) {
#pragma unroll
        for (int nt = 0; nt < 4; nt++) {
            int gr = row0 + 64 * wm + 16 * mt + (lane >> 2);
            int gc = col0 + 32 * wn + 8 * nt + 2 * (lane & 3);
            const float* cc = acc[mt][nt];
            if (OUT == 1) {
                *reinterpret_cast<uint32_t*>(&Ch[(size_t)gr * N + gc]) =
                    pack_h(cc[0], cc[1]);
                *reinterpret_cast<uint32_t*>(&Ch[(size_t)(gr + 8) * N + gc]) =
                    pack_h(cc[2], cc[3]);
            } else {
                float b0 = bias[gc], b1 = bias[gc + 1];
                *reinterpret_cast<float2*>(&Cf[(size_t)gr * N + gc]) =
                    make_float2(cc[0] + b0, cc[1] + b1);
                *reinterpret_cast<float2*>(&Cf[(size_t)(gr + 8) * N + gc]) =
                    make_float2(cc[2] + b0, cc[3] + b1);
            }
        }
    }
}
#define GEMM_SMEM ((int)sizeof(GemmSmem))

// ---------------------------------------------------------------------------
// Fused quadratic-ReLU attention, all single-plane fp16.
// CTA = 256 q-rows x (head, batch). 8 warps; warp w owns rows 32w..32w+31.
// S = QK^T 1 MMA; P,V single fp16 1 MMA. K/V double-buffered cp.async.
// ---------------------------------------------------------------------------
struct AttnSmem {
    __half Kh[2][128][72], Vh[2][128][72];
};

__device__ __forceinline__ void load_tile72_async(
    __half (*dst)[72], const __half* __restrict__ src, int tid)
{
#pragma unroll
    for (int l = 0; l < 4; l++) {
        int idx = tid + 256 * l;
        int r = idx >> 3, p = idx & 7;
        cp16(&dst[r][p * 8], &src[(size_t)r * QKV_N + p * 8]);
    }
}

__global__ void __launch_bounds__(256, 1)
attn_mma(const __half* __restrict__ qkv_hi,
         const float* __restrict__ alpha,
         const float* __restrict__ beta,
         const float* __restrict__ gamma,
         __half* __restrict__ att_hi)
{
    AttnSmem& s = *reinterpret_cast<AttnSmem*>(smem_raw);
    const int tid  = threadIdx.x;
    const int lane = tid & 31;
    const int w    = tid >> 5;
    const int qt   = blockIdx.x;
    const int h    = blockIdx.y;
    const int b    = blockIdx.z;
    const int q0   = qt * QB;

    const float av = alpha[h], bv = beta[h], gv = gamma[h];
    const size_t base = (size_t)(b * SEQ) * QKV_N + h * HD;

    load_tile72_async(s.Kh[0], qkv_hi + base + DIM,     tid);
    load_tile72_async(s.Vh[0], qkv_hi + base + 2 * DIM, tid);
    cp_commit();

    // Q fragments from global (A-frag layout per 16x16 k-tile)
    uint32_t qh[2][4][4];
    {
        const int rb = b * SEQ + q0 + 32 * w + (lane >> 2);
        const int cb = h * HD + 2 * (lane & 3);
#pragma unroll
        for (int rg = 0; rg < 2; rg++) {
#pragma unroll
            for (int kc = 0; kc < 4; kc++) {
                size_t o00 = (size_t)(rb + 16 * rg) * QKV_N + cb + 16 * kc;
                size_t o10 = o00 + 8 * QKV_N;
                qh[rg][kc][0] = *reinterpret_cast<const uint32_t*>(&qkv_hi[o00]);
                qh[rg][kc][1] = *reinterpret_cast<const uint32_t*>(&qkv_hi[o10]);
                qh[rg][kc][2] = *reinterpret_cast<const uint32_t*>(&qkv_hi[o00 + 8]);
                qh[rg][kc][3] = *reinterpret_cast<const uint32_t*>(&qkv_hi[o10 + 8]);
            }
        }
    }

    float O[2][8][4];
#pragma unroll
    for (int rg = 0; rg < 2; rg++)
#pragma unroll
        for (int j = 0; j < 8; j++)
#pragma unroll
            for (int q = 0; q < 4; q++) O[rg][j][q] = 0.f;
    float rs[2][2] = {{0.f, 0.f}, {0.f, 0.f}};

    for (int kt = 0; kt < SEQ / 128; kt++) {
        const int st = kt & 1;
        if (kt + 1 < SEQ / 128) {
            const size_t koff = base + (size_t)((kt + 1) * 128) * QKV_N;
            load_tile72_async(s.Kh[st ^ 1], qkv_hi + koff + DIM,     tid);
            load_tile72_async(s.Vh[st ^ 1], qkv_hi + koff + 2 * DIM, tid);
            cp_commit();
            cp_wait<1>();
        } else {
            cp_wait<0>();
        }
        __syncthreads();

#pragma unroll
        for (int rg = 0; rg < 2; rg++) {
            float S[16][4];
#pragma unroll
            for (int j = 0; j < 16; j++)
#pragma unroll
                for (int q = 0; q < 4; q++) S[j][q] = 0.f;

#pragma unroll
            for (int kc = 0; kc < 4; kc++) {
#pragma unroll
                for (int np = 0; np < 8; np++) {
                    uint32_t kh[4];
                    int r = 16 * np + (lane & 7) + (lane >> 4) * 8;
                    int c = 16 * kc + ((lane >> 3) & 1) * 8;
                    ldsm4(kh, sptr(&s.Kh[st][r][c]));
                    mma_f16(S[2 * np + 0], qh[rg][kc], kh[0], kh[1]);
                    mma_f16(S[2 * np + 1], qh[rg][kc], kh[2], kh[3]);
                }
            }

#pragma unroll
            for (int j = 0; j < 16; j++) {
#pragma unroll
                for (int q = 0; q < 4; q++) {
                    float z = S[j][q] * ATT_SCALE;
                    float p = fmaf(fmaf(av, z, bv), z, gv);
                    S[j][q] = fmaxf(p, 0.f);
                }
                rs[rg][0] += S[j][0] + S[j][1];
                rs[rg][1] += S[j][2] + S[j][3];
            }

#pragma unroll
            for (int c8 = 0; c8 < 8; c8++) {
                uint32_t ph[4];
                ph[0] = pack_h(S[2 * c8][0],     S[2 * c8][1]);
                ph[1] = pack_h(S[2 * c8][2],     S[2 * c8][3]);
                ph[2] = pack_h(S[2 * c8 + 1][0], S[2 * c8 + 1][1]);
                ph[3] = pack_h(S[2 * c8 + 1][2], S[2 * c8 + 1][3]);
#pragma unroll
                for (int ep = 0; ep < 4; ep++) {
                    uint32_t vh[4];
                    int r = 16 * c8 + (lane & 7) + ((lane >> 3) & 1) * 8;
                    int c = 16 * ep + (lane >> 4) * 8;
                    ldsm4t(vh, sptr(&s.Vh[st][r][c]));
                    mma_f16(O[rg][2 * ep + 0], ph, vh[0], vh[1]);
                    mma_f16(O[rg][2 * ep + 1], ph, vh[2], vh[3]);
                }
            }
        }
        __syncthreads();
    }

#pragma unroll
    for (int rg = 0; rg < 2; rg++) {
        float r0 = rs[rg][0], r1 = rs[rg][1];
        r0 += __shfl_xor_sync(0xffffffffu, r0, 1);
        r0 += __shfl_xor_sync(0xffffffffu, r0, 2);
        r1 += __shfl_xor_sync(0xffffffffu, r1, 1);
        r1 += __shfl_xor_sync(0xffffffffu, r1, 2);
        const float inv0 = 1.f / (r0 + 1e-6f);
        const float inv1 = 1.f / (r1 + 1e-6f);

        const int row = b * SEQ + q0 + 32 * w + 16 * rg + (lane >> 2);
#pragma unroll
        for (int j = 0; j < 8; j++) {
            int ce = h * HD + 8 * j + 2 * (lane & 3);
            *reinterpret_cast<uint32_t*>(&att_hi[(size_t)row * DIM + ce]) =
                pack_h(O[rg][j][0] * inv0, O[rg][j][1] * inv0);
            *reinterpret_cast<uint32_t*>(&att_hi[(size_t)(row + 8) * DIM + ce]) =
                pack_h(O[rg][j][2] * inv1, O[rg][j][3] * inv1);
        }
    }
}

// ---------------------------------------------------------------------------
// Launch
// ---------------------------------------------------------------------------
extern "C" void kernel_launch(void* const* d_in, const int* in_sizes, int n_in,
                              void* d_out, int out_size)
{
    const float* x      = (const float*)d_in[0];
    const float* w_qkv  = (const float*)d_in[1];
    const float* w_proj = (const float*)d_in[2];
    const float* b_proj = (const float*)d_in[3];
    const float* alpha  = (const float*)d_in[4];
    const float* beta   = (const float*)d_in[5];
    const float* gamma  = (const float*)d_in[6];
    float* out = (float*)d_out;

    __half *xh, *wqh, *wph, *qh, *ah;
    cudaGetSymbolAddress((void**)&xh,  g_x_hi);
    cudaGetSymbolAddress((void**)&wqh, g_wqkv_hi);
    cudaGetSymbolAddress((void**)&wph, g_wproj_hi);
    cudaGetSymbolAddress((void**)&qh,  g_qkv_hi);
    cudaGetSymbolAddress((void**)&ah,  g_att_hi);

    cudaFuncSetAttribute((const void*)gemm_f16<1>,
                         cudaFuncAttributeMaxDynamicSharedMemorySize, GEMM_SMEM);
    cudaFuncSetAttribute((const void*)gemm_f16<0>,
                         cudaFuncAttributeMaxDynamicSharedMemorySize, GEMM_SMEM);
    cudaFuncSetAttribute((const void*)attn_mma,
                         cudaFuncAttributeMaxDynamicSharedMemorySize,
                         (int)sizeof(AttnSmem));

    // 0) fp32 -> fp16 hi planes
    {
        int n4 = M_TOT * DIM / 4;
        to_half_kernel<<<(n4 + 255) / 256, 256>>>((const float4*)x,
                                                  (uint2*)xh, n4);
        n4 = QKV_N * DIM / 4;
        to_half_kernel<<<(n4 + 255) / 256, 256>>>((const float4*)w_qkv,
                                                  (uint2*)wqh, n4);
        n4 = DIM * DIM / 4;
        to_half_kernel<<<(n4 + 255) / 256, 256>>>((const float4*)w_proj,
                                                  (uint2*)wph, n4);
    }

    // 1) QKV projection -> fp16 plane
    {
        dim3 grid(QKV_N / 128, M_TOT / 128);
        gemm_f16<1><<<grid, 256, GEMM_SMEM>>>(
            xh, wqh, nullptr, qh, nullptr, M_TOT, QKV_N, DIM);
    }

    // 2) Fused quadratic attention -> fp16 plane
    {
        dim3 grid(SEQ / QB, NH, BB);
        attn_mma<<<grid, 256, sizeof(AttnSmem)>>>(qh, alpha, beta, gamma, ah);
    }

    // 3) Output projection + bias -> fp32 out
    {
        dim3 grid(DIM / 128, M_TOT / 128);
        gemm_f16<0><<<grid, 256, GEMM_SMEM>>>(
            ah, wph, b_proj, nullptr, out, M_TOT, DIM, DIM);
    }
}

// round 10
// speedup vs baseline: 2.3793x; 1.0132x over previous
#include <cuda_runtime.h>
#include <cuda_fp16.h>
#include <cstdint>
#include <cstddef>

#define DIM      768
#define NH       12
#define HD       64
#define BB       8
#define SEQ      1024
#define M_TOT    (BB * SEQ)          // 8192
#define QKV_N    (3 * DIM)           // 2304
#define ATT_SCALE 0.125f
#define QB       256                 // q rows per attention CTA

// ---------------------------------------------------------------------------
// Scratch planes. Device globals: allocation-free.
// ---------------------------------------------------------------------------
__device__ __half g_x_hi[(size_t)M_TOT * DIM];
__device__ __half g_wqkv_hi[(size_t)QKV_N * DIM];
__device__ __half g_wproj_hi[(size_t)DIM * DIM];
__device__ __half g_qkv_hi[(size_t)M_TOT * QKV_N];
__device__ __half g_att_hi[(size_t)M_TOT * DIM];

// ---------------------------------------------------------------------------
// Helpers
// ---------------------------------------------------------------------------
__device__ __forceinline__ uint32_t sptr(const void* p) {
    return (uint32_t)__cvta_generic_to_shared(p);
}
__device__ __forceinline__ void cp16(void* dst, const void* src) {
    asm volatile("cp.async.cg.shared.global [%0], [%1], 16;"
                 :: "r"(sptr(dst)), "l"(src));
}
__device__ __forceinline__ void cp_commit() {
    asm volatile("cp.async.commit_group;");
}
template<int N>
__device__ __forceinline__ void cp_wait() {
    asm volatile("cp.async.wait_group %0;" :: "n"(N));
}
__device__ __forceinline__ void ldsm4(uint32_t r[4], uint32_t a) {
    asm volatile("ldmatrix.sync.aligned.m8n8.x4.shared.b16 {%0,%1,%2,%3}, [%4];"
                 : "=r"(r[0]), "=r"(r[1]), "=r"(r[2]), "=r"(r[3]) : "r"(a));
}
__device__ __forceinline__ void ldsm4t(uint32_t r[4], uint32_t a) {
    asm volatile("ldmatrix.sync.aligned.m8n8.x4.trans.shared.b16 {%0,%1,%2,%3}, [%4];"
                 : "=r"(r[0]), "=r"(r[1]), "=r"(r[2]), "=r"(r[3]) : "r"(a));
}
__device__ __forceinline__ void mma_f16(float c[4], const uint32_t a[4],
                                        uint32_t b0, uint32_t b1) {
    asm volatile(
        "mma.sync.aligned.m16n8k16.row.col.f32.f16.f16.f32 "
        "{%0,%1,%2,%3},{%4,%5,%6,%7},{%8,%9},{%0,%1,%2,%3};"
        : "+f"(c[0]), "+f"(c[1]), "+f"(c[2]), "+f"(c[3])
        : "r"(a[0]), "r"(a[1]), "r"(a[2]), "r"(a[3]), "r"(b0), "r"(b1));
}
__device__ __forceinline__ uint32_t pack_h(float a, float b) {
    __half2 t = __floats2half2_rn(a, b);
    return *reinterpret_cast<uint32_t*>(&t);
}

// ---------------------------------------------------------------------------
// Fused fp32 -> fp16 conversion for all three inputs (one launch).
// ---------------------------------------------------------------------------
#define N4_X   (M_TOT * DIM / 4)     // 1572864
#define N4_WQ  (QKV_N * DIM / 4)     //  442368
#define N4_WP  (DIM * DIM / 4)       //  147456
#define N4_ALL (N4_X + N4_WQ + N4_WP)

__global__ void to_half_all(const float4* __restrict__ x,
                            const float4* __restrict__ wq,
                            const float4* __restrict__ wp,
                            uint2* __restrict__ xh,
                            uint2* __restrict__ wqh,
                            uint2* __restrict__ wph) {
    int i = blockIdx.x * blockDim.x + threadIdx.x;
    const float4* src;
    uint2* dst;
    int j;
    if (i < N4_X)                { src = x;  dst = xh;  j = i; }
    else if (i < N4_X + N4_WQ)   { src = wq; dst = wqh; j = i - N4_X; }
    else if (i < N4_ALL)         { src = wp; dst = wph; j = i - N4_X - N4_WQ; }
    else return;
    float4 v = src[j];
    dst[j] = make_uint2(pack_h(v.x, v.y), pack_h(v.z, v.w));
}

// ---------------------------------------------------------------------------
// fp16 tensor-core GEMM, cp.async 2-stage, BK=64, CTA tile MT x 128.
// C[M,N] = A[M,K] * B[N,K]^T. 8 warps (2m x 4n); warp tile (MT/2) x 32.
// OUT=0: fp32 + bias. OUT=1: fp16 plane.
// MT=128: occ 2 (72KB smem). MT=64: occ 3 (54KB smem).
// ---------------------------------------------------------------------------
template<int MT> struct GemmSmemT {
    __half Ah[2][MT][72], Bh[2][128][72];
};
extern __shared__ __align__(1024) char smem_raw[];

template<int MT>
__device__ __forceinline__ void gemm_load_stage(
    GemmSmemT<MT>& s, int st,
    const __half* __restrict__ Ah_g, const __half* __restrict__ Bh_g,
    int row0, int col0, int K, int k0, int tid)
{
#pragma unroll
    for (int l = 0; l < MT / 32; l++) {          // A: MT*8 slots
        int idx = tid + 256 * l;
        int r = idx >> 3, p = idx & 7;
        cp16(&s.Ah[st][r][p * 8], &Ah_g[(size_t)(row0 + r) * K + k0 + p * 8]);
    }
#pragma unroll
    for (int l = 0; l < 4; l++) {                // B: 1024 slots
        int idx = tid + 256 * l;
        int r = idx >> 3, p = idx & 7;
        cp16(&s.Bh[st][r][p * 8], &Bh_g[(size_t)(col0 + r) * K + k0 + p * 8]);
    }
}

template<int OUT, int MT>
__global__ void __launch_bounds__(256, (MT == 64) ? 3 : 2)
gemm_f16(const __half* __restrict__ Ah_g,
         const __half* __restrict__ Bh_g,
         const float* __restrict__ bias,
         __half* __restrict__ Ch,
         float* __restrict__ Cf,
         int M, int N, int K)
{
    GemmSmemT<MT>& s = *reinterpret_cast<GemmSmemT<MT>*>(smem_raw);
    constexpr int NMT = MT / 32;     // 16-row m-tiles per warp

    const int tid  = threadIdx.x;
    const int lane = tid & 31;
    const int w    = tid >> 5;
    const int wm   = w & 1;
    const int wn   = w >> 1;
    const int row0 = blockIdx.y * MT;
    const int col0 = blockIdx.x * 128;

    float acc[NMT][4][4];
#pragma unroll
    for (int a = 0; a < NMT; a++)
#pragma unroll
        for (int b = 0; b < 4; b++)
#pragma unroll
            for (int c = 0; c < 4; c++) acc[a][b][c] = 0.f;

    const int nk = K / 64;
    gemm_load_stage<MT>(s, 0, Ah_g, Bh_g, row0, col0, K, 0, tid);
    cp_commit();

    for (int i = 0; i < nk; i++) {
        const int st = i & 1;
        if (i + 1 < nk) {
            gemm_load_stage<MT>(s, st ^ 1, Ah_g, Bh_g, row0, col0, K,
                                (i + 1) * 64, tid);
            cp_commit();
            cp_wait<1>();
        } else {
            cp_wait<0>();
        }
        __syncthreads();

#pragma unroll
        for (int kk = 0; kk < 64; kk += 16) {
            uint32_t ah[NMT][4];
#pragma unroll
            for (int mt = 0; mt < NMT; mt++) {
                int r = (MT / 2) * wm + 16 * mt + (lane & 15);
                int c = kk + (lane >> 4) * 8;
                ldsm4(ah[mt], sptr(&s.Ah[st][r][c]));
            }
#pragma unroll
            for (int np = 0; np < 2; np++) {
                uint32_t bh[4];
                int r = 32 * wn + 16 * np + (lane & 7) + (lane >> 4) * 8;
                int c = kk + ((lane >> 3) & 1) * 8;
                ldsm4(bh, sptr(&s.Bh[st][r][c]));
#pragma unroll
                for (int mt = 0; mt < NMT; mt++) {
                    mma_f16(acc[mt][2 * np + 0], ah[mt], bh[0], bh[1]);
                    mma_f16(acc[mt][2 * np + 1], ah[mt], bh[2], bh[3]);
                }
            }
        }
        __syncthreads();
    }

    // Epilogue
#pragma unroll
    for (int mt = 0; mt < NMT; mt++) {
#pragma unroll
        for (int nt = 0; nt < 4; nt++) {
            int gr = row0 + (MT / 2) * wm + 16 * mt + (lane >> 2);
            int gc = col0 + 32 * wn + 8 * nt + 2 * (lane & 3);
            const float* cc = acc[mt][nt];
            if (OUT == 1) {
                *reinterpret_cast<uint32_t*>(&Ch[(size_t)gr * N + gc]) =
                    pack_h(cc[0], cc[1]);
                *reinterpret_cast<uint32_t*>(&Ch[(size_t)(gr + 8) * N + gc]) =
                    pack_h(cc[2], cc[3]);
            } else {
                float b0 = bias[gc], b1 = bias[gc + 1];
                *reinterpret_cast<float2*>(&Cf[(size_t)gr * N + gc]) =
                    make_float2(cc[0] + b0, cc[1] + b1);
                *reinterpret_cast<float2*>(&Cf[(size_t)(gr + 8) * N + gc]) =
                    make_float2(cc[2] + b0, cc[3] + b1);
            }
        }
    }
}

// ---------------------------------------------------------------------------
// Fused quadratic-ReLU attention, all single-plane fp16 (unchanged from R9).
// ---------------------------------------------------------------------------
struct AttnSmem {
    __half Kh[2][128][72], Vh[2][128][72];
};

__device__ __forceinline__ void load_tile72_async(
    __half (*dst)[72], const __half* __restrict__ src, int tid)
{
#pragma unroll
    for (int l = 0; l < 4; l++) {
        int idx = tid + 256 * l;
        int r = idx >> 3, p = idx & 7;
        cp16(&dst[r][p * 8], &src[(size_t)r * QKV_N + p * 8]);
    }
}

__global__ void __launch_bounds__(256, 1)
attn_mma(const __half* __restrict__ qkv_hi,
         const float* __restrict__ alpha,
         const float* __restrict__ beta,
         const float* __restrict__ gamma,
         __half* __restrict__ att_hi)
{
    AttnSmem& s = *reinterpret_cast<AttnSmem*>(smem_raw);
    const int tid  = threadIdx.x;
    const int lane = tid & 31;
    const int w    = tid >> 5;
    const int qt   = blockIdx.x;
    const int h    = blockIdx.y;
    const int b    = blockIdx.z;
    const int q0   = qt * QB;

    const float av = alpha[h], bv = beta[h], gv = gamma[h];
    const size_t base = (size_t)(b * SEQ) * QKV_N + h * HD;

    load_tile72_async(s.Kh[0], qkv_hi + base + DIM,     tid);
    load_tile72_async(s.Vh[0], qkv_hi + base + 2 * DIM, tid);
    cp_commit();

    uint32_t qh[2][4][4];
    {
        const int rb = b * SEQ + q0 + 32 * w + (lane >> 2);
        const int cb = h * HD + 2 * (lane & 3);
#pragma unroll
        for (int rg = 0; rg < 2; rg++) {
#pragma unroll
            for (int kc = 0; kc < 4; kc++) {
                size_t o00 = (size_t)(rb + 16 * rg) * QKV_N + cb + 16 * kc;
                size_t o10 = o00 + 8 * QKV_N;
                qh[rg][kc][0] = *reinterpret_cast<const uint32_t*>(&qkv_hi[o00]);
                qh[rg][kc][1] = *reinterpret_cast<const uint32_t*>(&qkv_hi[o10]);
                qh[rg][kc][2] = *reinterpret_cast<const uint32_t*>(&qkv_hi[o00 + 8]);
                qh[rg][kc][3] = *reinterpret_cast<const uint32_t*>(&qkv_hi[o10 + 8]);
            }
        }
    }

    float O[2][8][4];
#pragma unroll
    for (int rg = 0; rg < 2; rg++)
#pragma unroll
        for (int j = 0; j < 8; j++)
#pragma unroll
            for (int q = 0; q < 4; q++) O[rg][j][q] = 0.f;
    float rs[2][2] = {{0.f, 0.f}, {0.f, 0.f}};

    for (int kt = 0; kt < SEQ / 128; kt++) {
        const int st = kt & 1;
        if (kt + 1 < SEQ / 128) {
            const size_t koff = base + (size_t)((kt + 1) * 128) * QKV_N;
            load_tile72_async(s.Kh[st ^ 1], qkv_hi + koff + DIM,     tid);
            load_tile72_async(s.Vh[st ^ 1], qkv_hi + koff + 2 * DIM, tid);
            cp_commit();
            cp_wait<1>();
        } else {
            cp_wait<0>();
        }
        __syncthreads();

#pragma unroll
        for (int rg = 0; rg < 2; rg++) {
            float S[16][4];
#pragma unroll
            for (int j = 0; j < 16; j++)
#pragma unroll
                for (int q = 0; q < 4; q++) S[j][q] = 0.f;

#pragma unroll
            for (int kc = 0; kc < 4; kc++) {
#pragma unroll
                for (int np = 0; np < 8; np++) {
                    uint32_t kh[4];
                    int r = 16 * np + (lane & 7) + (lane >> 4) * 8;
                    int c = 16 * kc + ((lane >> 3) & 1) * 8;
                    ldsm4(kh, sptr(&s.Kh[st][r][c]));
                    mma_f16(S[2 * np + 0], qh[rg][kc], kh[0], kh[1]);
                    mma_f16(S[2 * np + 1], qh[rg][kc], kh[2], kh[3]);
                }
            }

#pragma unroll
            for (int j = 0; j < 16; j++) {
#pragma unroll
                for (int q = 0; q < 4; q++) {
                    float z = S[j][q] * ATT_SCALE;
                    float p = fmaf(fmaf(av, z, bv), z, gv);
                    S[j][q] = fmaxf(p, 0.f);
                }
                rs[rg][0] += S[j][0] + S[j][1];
                rs[rg][1] += S[j][2] + S[j][3];
            }

#pragma unroll
            for (int c8 = 0; c8 < 8; c8++) {
                uint32_t ph[4];
                ph[0] = pack_h(S[2 * c8][0],     S[2 * c8][1]);
                ph[1] = pack_h(S[2 * c8][2],     S[2 * c8][3]);
                ph[2] = pack_h(S[2 * c8 + 1][0], S[2 * c8 + 1][1]);
                ph[3] = pack_h(S[2 * c8 + 1][2], S[2 * c8 + 1][3]);
#pragma unroll
                for (int ep = 0; ep < 4; ep++) {
                    uint32_t vh[4];
                    int r = 16 * c8 + (lane & 7) + ((lane >> 3) & 1) * 8;
                    int c = 16 * ep + (lane >> 4) * 8;
                    ldsm4t(vh, sptr(&s.Vh[st][r][c]));
                    mma_f16(O[rg][2 * ep + 0], ph, vh[0], vh[1]);
                    mma_f16(O[rg][2 * ep + 1], ph, vh[2], vh[3]);
                }
            }
        }
        __syncthreads();
    }

#pragma unroll
    for (int rg = 0; rg < 2; rg++) {
        float r0 = rs[rg][0], r1 = rs[rg][1];
        r0 += __shfl_xor_sync(0xffffffffu, r0, 1);
        r0 += __shfl_xor_sync(0xffffffffu, r0, 2);
        r1 += __shfl_xor_sync(0xffffffffu, r1, 1);
        r1 += __shfl_xor_sync(0xffffffffu, r1, 2);
        const float inv0 = 1.f / (r0 + 1e-6f);
        const float inv1 = 1.f / (r1 + 1e-6f);

        const int row = b * SEQ + q0 + 32 * w + 16 * rg + (lane >> 2);
#pragma unroll
        for (int j = 0; j < 8; j++) {
            int ce = h * HD + 8 * j + 2 * (lane & 3);
            *reinterpret_cast<uint32_t*>(&att_hi[(size_t)row * DIM + ce]) =
                pack_h(O[rg][j][0] * inv0, O[rg][j][1] * inv0);
            *reinterpret_cast<uint32_t*>(&att_hi[(size_t)(row + 8) * DIM + ce]) =
                pack_h(O[rg][j][2] * inv1, O[rg][j][3] * inv1);
        }
    }
}

// ---------------------------------------------------------------------------
// Launch
// ---------------------------------------------------------------------------
extern "C" void kernel_launch(void* const* d_in, const int* in_sizes, int n_in,
                              void* d_out, int out_size)
{
    const float* x      = (const float*)d_in[0];
    const float* w_qkv  = (const float*)d_in[1];
    const float* w_proj = (const float*)d_in[2];
    const float* b_proj = (const float*)d_in[3];
    const float* alpha  = (const float*)d_in[4];
    const float* beta   = (const float*)d_in[5];
    const float* gamma  = (const float*)d_in[6];
    float* out = (float*)d_out;

    __half *xh, *wqh, *wph, *qh, *ah;
    cudaGetSymbolAddress((void**)&xh,  g_x_hi);
    cudaGetSymbolAddress((void**)&wqh, g_wqkv_hi);
    cudaGetSymbolAddress((void**)&wph, g_wproj_hi);
    cudaGetSymbolAddress((void**)&qh,  g_qkv_hi);
    cudaGetSymbolAddress((void**)&ah,  g_att_hi);

    cudaFuncSetAttribute((const void*)gemm_f16<1, 128>,
                         cudaFuncAttributeMaxDynamicSharedMemorySize,
                         (int)sizeof(GemmSmemT<128>));
    cudaFuncSetAttribute((const void*)gemm_f16<0, 64>,
                         cudaFuncAttributeMaxDynamicSharedMemorySize,
                         (int)sizeof(GemmSmemT<64>));
    cudaFuncSetAttribute((const void*)attn_mma,
                         cudaFuncAttributeMaxDynamicSharedMemorySize,
                         (int)sizeof(AttnSmem));

    // 0) fp32 -> fp16 planes, one launch for all three tensors
    to_half_all<<<N4_ALL / 256, 256>>>((const float4*)x, (const float4*)w_qkv,
                                       (const float4*)w_proj,
                                       (uint2*)xh, (uint2*)wqh, (uint2*)wph);

    // 1) QKV projection -> fp16 plane (128x128 tiles, occ 2, ~97% waves)
    {
        dim3 grid(QKV_N / 128, M_TOT / 128);
        gemm_f16<1, 128><<<grid, 256, sizeof(GemmSmemT<128>)>>>(
            xh, wqh, nullptr, qh, nullptr, M_TOT, QKV_N, DIM);
    }

    // 2) Fused quadratic attention -> fp16 plane
    {
        dim3 grid(SEQ / QB, NH, BB);
        attn_mma<<<grid, 256, sizeof(AttnSmem)>>>(qh, alpha, beta, gamma, ah);
    }

    // 3) Output projection + bias -> fp32 out (64x128 tiles, occ 3, ~87% waves)
    {
        dim3 grid(DIM / 128, M_TOT / 64);
        gemm_f16<0, 64><<<grid, 256, sizeof(GemmSmemT<64>)>>>(
            ah, wph, b_proj, nullptr, out, M_TOT, DIM, DIM);
    }
}

// round 11
// speedup vs baseline: 2.3909x; 1.0049x over previous
#include <cuda_runtime.h>
#include <cuda_fp16.h>
#include <cstdint>
#include <cstddef>

#define DIM      768
#define NH       12
#define HD       64
#define BB       8
#define SEQ      1024
#define M_TOT    (BB * SEQ)          // 8192
#define QKV_N    (3 * DIM)           // 2304
#define ATT_SCALE 0.125f
#define QB       256                 // q rows per attention CTA

// ---------------------------------------------------------------------------
// Scratch planes. Device globals: allocation-free.
// ---------------------------------------------------------------------------
__device__ __half g_x_hi[(size_t)M_TOT * DIM];
__device__ __half g_wqkv_hi[(size_t)QKV_N * DIM];
__device__ __half g_wproj_hi[(size_t)DIM * DIM];
__device__ __half g_qkv_hi[(size_t)M_TOT * QKV_N];
__device__ __half g_att_hi[(size_t)M_TOT * DIM];

// ---------------------------------------------------------------------------
// Helpers
// ---------------------------------------------------------------------------
__device__ __forceinline__ uint32_t sptr(const void* p) {
    return (uint32_t)__cvta_generic_to_shared(p);
}
__device__ __forceinline__ void cp16(void* dst, const void* src) {
    asm volatile("cp.async.cg.shared.global [%0], [%1], 16;"
                 :: "r"(sptr(dst)), "l"(src));
}
__device__ __forceinline__ void cp_commit() {
    asm volatile("cp.async.commit_group;");
}
template<int N>
__device__ __forceinline__ void cp_wait() {
    asm volatile("cp.async.wait_group %0;" :: "n"(N));
}
__device__ __forceinline__ void ldsm4(uint32_t r[4], uint32_t a) {
    asm volatile("ldmatrix.sync.aligned.m8n8.x4.shared.b16 {%0,%1,%2,%3}, [%4];"
                 : "=r"(r[0]), "=r"(r[1]), "=r"(r[2]), "=r"(r[3]) : "r"(a));
}
__device__ __forceinline__ void ldsm4t(uint32_t r[4], uint32_t a) {
    asm volatile("ldmatrix.sync.aligned.m8n8.x4.trans.shared.b16 {%0,%1,%2,%3}, [%4];"
                 : "=r"(r[0]), "=r"(r[1]), "=r"(r[2]), "=r"(r[3]) : "r"(a));
}
__device__ __forceinline__ void mma_f16(float c[4], const uint32_t a[4],
                                        uint32_t b0, uint32_t b1) {
    asm volatile(
        "mma.sync.aligned.m16n8k16.row.col.f32.f16.f16.f32 "
        "{%0,%1,%2,%3},{%4,%5,%6,%7},{%8,%9},{%0,%1,%2,%3};"
        : "+f"(c[0]), "+f"(c[1]), "+f"(c[2]), "+f"(c[3])
        : "r"(a[0]), "r"(a[1]), "r"(a[2]), "r"(a[3]), "r"(b0), "r"(b1));
}
__device__ __forceinline__ uint32_t pack_h(float a, float b) {
    __half2 t = __floats2half2_rn(a, b);
    return *reinterpret_cast<uint32_t*>(&t);
}

// ---------------------------------------------------------------------------
// Fused fp32 -> fp16 conversion for all three inputs (one launch).
// ---------------------------------------------------------------------------
#define N4_X   (M_TOT * DIM / 4)     // 1572864
#define N4_WQ  (QKV_N * DIM / 4)     //  442368
#define N4_WP  (DIM * DIM / 4)       //  147456
#define N4_ALL (N4_X + N4_WQ + N4_WP)

__global__ void to_half_all(const float4* __restrict__ x,
                            const float4* __restrict__ wq,
                            const float4* __restrict__ wp,
                            uint2* __restrict__ xh,
                            uint2* __restrict__ wqh,
                            uint2* __restrict__ wph) {
    int i = blockIdx.x * blockDim.x + threadIdx.x;
    const float4* src;
    uint2* dst;
    int j;
    if (i < N4_X)                { src = x;  dst = xh;  j = i; }
    else if (i < N4_X + N4_WQ)   { src = wq; dst = wqh; j = i - N4_X; }
    else if (i < N4_ALL)         { src = wp; dst = wph; j = i - N4_X - N4_WQ; }
    else return;
    float4 v = src[j];
    dst[j] = make_uint2(pack_h(v.x, v.y), pack_h(v.z, v.w));
}

// ---------------------------------------------------------------------------
// fp16 tensor-core GEMM, cp.async pipeline (ST stages), BK=64, CTA tile MTx128.
// C[M,N] = A[M,K] * B[N,K]^T. 8 warps (2m x 4n); warp tile (MT/2) x 32.
// ST=3: single __syncthreads per K-chunk. ST=2: classic two-sync.
// OUT=0: fp32 + bias. OUT=1: fp16 plane.
// ---------------------------------------------------------------------------
template<int MT, int ST> struct GemmSmemT {
    __half Ah[ST][MT][72], Bh[ST][128][72];
};
extern __shared__ __align__(1024) char smem_raw[];

template<int MT, int ST>
__device__ __forceinline__ void gemm_load_stage(
    GemmSmemT<MT, ST>& s, int st,
    const __half* __restrict__ Ah_g, const __half* __restrict__ Bh_g,
    int row0, int col0, int K, int k0, int tid)
{
#pragma unroll
    for (int l = 0; l < MT / 32; l++) {          // A: MT*8 slots
        int idx = tid + 256 * l;
        int r = idx >> 3, p = idx & 7;
        cp16(&s.Ah[st][r][p * 8], &Ah_g[(size_t)(row0 + r) * K + k0 + p * 8]);
    }
#pragma unroll
    for (int l = 0; l < 4; l++) {                // B: 1024 slots
        int idx = tid + 256 * l;
        int r = idx >> 3, p = idx & 7;
        cp16(&s.Bh[st][r][p * 8], &Bh_g[(size_t)(col0 + r) * K + k0 + p * 8]);
    }
}

template<int OUT, int MT, int ST>
__global__ void __launch_bounds__(256, (MT == 64) ? 3 : 2)
gemm_f16(const __half* __restrict__ Ah_g,
         const __half* __restrict__ Bh_g,
         const float* __restrict__ bias,
         __half* __restrict__ Ch,
         float* __restrict__ Cf,
         int M, int N, int K)
{
    GemmSmemT<MT, ST>& s = *reinterpret_cast<GemmSmemT<MT, ST>*>(smem_raw);
    constexpr int NMT = MT / 32;     // 16-row m-tiles per warp

    const int tid  = threadIdx.x;
    const int lane = tid & 31;
    const int w    = tid >> 5;
    const int wm   = w & 1;
    const int wn   = w >> 1;
    const int row0 = blockIdx.y * MT;
    const int col0 = blockIdx.x * 128;

    float acc[NMT][4][4];
#pragma unroll
    for (int a = 0; a < NMT; a++)
#pragma unroll
        for (int b = 0; b < 4; b++)
#pragma unroll
            for (int c = 0; c < 4; c++) acc[a][b][c] = 0.f;

    const int nk = K / 64;

    if (ST == 3) {
        gemm_load_stage(s, 0, Ah_g, Bh_g, row0, col0, K, 0, tid);
        cp_commit();
        gemm_load_stage(s, 1, Ah_g, Bh_g, row0, col0, K, 64, tid);
        cp_commit();
    } else {
        gemm_load_stage(s, 0, Ah_g, Bh_g, row0, col0, K, 0, tid);
        cp_commit();
    }

    int st = 0;
    for (int i = 0; i < nk; i++) {
        if (ST == 3) {
            // pending groups at entry: {i, i+1} (i+1 exists iff i < nk-1)
            if (i < nk - 1) cp_wait<1>(); else cp_wait<0>();
            __syncthreads();   // stage i visible; stage (i+2)%3 drained
            if (i + 2 < nk) {
                int ns = st + 2; if (ns >= 3) ns -= 3;
                gemm_load_stage(s, ns, Ah_g, Bh_g, row0, col0, K,
                                (i + 2) * 64, tid);
                cp_commit();
            }
        } else {
            if (i + 1 < nk) {
                gemm_load_stage(s, st ^ 1, Ah_g, Bh_g, row0, col0, K,
                                (i + 1) * 64, tid);
                cp_commit();
                cp_wait<1>();
            } else {
                cp_wait<0>();
            }
            __syncthreads();
        }

#pragma unroll
        for (int kk = 0; kk < 64; kk += 16) {
            uint32_t ah[NMT][4];
#pragma unroll
            for (int mt = 0; mt < NMT; mt++) {
                int r = (MT / 2) * wm + 16 * mt + (lane & 15);
                int c = kk + (lane >> 4) * 8;
                ldsm4(ah[mt], sptr(&s.Ah[st][r][c]));
            }
#pragma unroll
            for (int np = 0; np < 2; np++) {
                uint32_t bh[4];
                int r = 32 * wn + 16 * np + (lane & 7) + (lane >> 4) * 8;
                int c = kk + ((lane >> 3) & 1) * 8;
                ldsm4(bh, sptr(&s.Bh[st][r][c]));
#pragma unroll
                for (int mt = 0; mt < NMT; mt++) {
                    mma_f16(acc[mt][2 * np + 0], ah[mt], bh[0], bh[1]);
                    mma_f16(acc[mt][2 * np + 1], ah[mt], bh[2], bh[3]);
                }
            }
        }

        if (ST == 3) {
            if (++st == 3) st = 0;
        } else {
            __syncthreads();
            st ^= 1;
        }
    }

    // Epilogue
#pragma unroll
    for (int mt = 0; mt < NMT; mt++) {
#pragma unroll
        for (int nt = 0; nt < 4; nt++) {
            int gr = row0 + (MT / 2) * wm + 16 * mt + (lane >> 2);
            int gc = col0 + 32 * wn + 8 * nt + 2 * (lane & 3);
            const float* cc = acc[mt][nt];
            if (OUT == 1) {
                *reinterpret_cast<uint32_t*>(&Ch[(size_t)gr * N + gc]) =
                    pack_h(cc[0], cc[1]);
                *reinterpret_cast<uint32_t*>(&Ch[(size_t)(gr + 8) * N + gc]) =
                    pack_h(cc[2], cc[3]);
            } else {
                float b0 = bias[gc], b1 = bias[gc + 1];
                *reinterpret_cast<float2*>(&Cf[(size_t)gr * N + gc]) =
                    make_float2(cc[0] + b0, cc[1] + b1);
                *reinterpret_cast<float2*>(&Cf[(size_t)(gr + 8) * N + gc]) =
                    make_float2(cc[2] + b0, cc[3] + b1);
            }
        }
    }
}

// ---------------------------------------------------------------------------
// Fused quadratic-ReLU attention, single-plane fp16, 3-stage K/V pipeline
// with one __syncthreads per key tile.
// CTA = 256 q-rows x (head, batch). 8 warps; warp w owns rows 32w..32w+31.
// ---------------------------------------------------------------------------
struct AttnSmem {
    __half Kh[3][128][72], Vh[3][128][72];
};

__device__ __forceinline__ void load_tile72_async(
    __half (*dst)[72], const __half* __restrict__ src, int tid)
{
#pragma unroll
    for (int l = 0; l < 4; l++) {
        int idx = tid + 256 * l;
        int r = idx >> 3, p = idx & 7;
        cp16(&dst[r][p * 8], &src[(size_t)r * QKV_N + p * 8]);
    }
}

__global__ void __launch_bounds__(256, 1)
attn_mma(const __half* __restrict__ qkv_hi,
         const float* __restrict__ alpha,
         const float* __restrict__ beta,
         const float* __restrict__ gamma,
         __half* __restrict__ att_hi)
{
    AttnSmem& s = *reinterpret_cast<AttnSmem*>(smem_raw);
    const int tid  = threadIdx.x;
    const int lane = tid & 31;
    const int w    = tid >> 5;
    const int qt   = blockIdx.x;
    const int h    = blockIdx.y;
    const int b    = blockIdx.z;
    const int q0   = qt * QB;
    const int NKT  = SEQ / 128;      // 8 key tiles

    const float av = alpha[h], bv = beta[h], gv = gamma[h];
    const size_t base = (size_t)(b * SEQ) * QKV_N + h * HD;

    // Prologue: prefetch key tiles 0 and 1
    load_tile72_async(s.Kh[0], qkv_hi + base + DIM,     tid);
    load_tile72_async(s.Vh[0], qkv_hi + base + 2 * DIM, tid);
    cp_commit();
    {
        const size_t koff = base + (size_t)128 * QKV_N;
        load_tile72_async(s.Kh[1], qkv_hi + koff + DIM,     tid);
        load_tile72_async(s.Vh[1], qkv_hi + koff + 2 * DIM, tid);
        cp_commit();
    }

    // Q fragments from global (A-frag layout per 16x16 k-tile)
    uint32_t qh[2][4][4];
    {
        const int rb = b * SEQ + q0 + 32 * w + (lane >> 2);
        const int cb = h * HD + 2 * (lane & 3);
#pragma unroll
        for (int rg = 0; rg < 2; rg++) {
#pragma unroll
            for (int kc = 0; kc < 4; kc++) {
                size_t o00 = (size_t)(rb + 16 * rg) * QKV_N + cb + 16 * kc;
                size_t o10 = o00 + 8 * QKV_N;
                qh[rg][kc][0] = *reinterpret_cast<const uint32_t*>(&qkv_hi[o00]);
                qh[rg][kc][1] = *reinterpret_cast<const uint32_t*>(&qkv_hi[o10]);
                qh[rg][kc][2] = *reinterpret_cast<const uint32_t*>(&qkv_hi[o00 + 8]);
                qh[rg][kc][3] = *reinterpret_cast<const uint32_t*>(&qkv_hi[o10 + 8]);
            }
        }
    }

    float O[2][8][4];
#pragma unroll
    for (int rg = 0; rg < 2; rg++)
#pragma unroll
        for (int j = 0; j < 8; j++)
#pragma unroll
            for (int q = 0; q < 4; q++) O[rg][j][q] = 0.f;
    float rs[2][2] = {{0.f, 0.f}, {0.f, 0.f}};

    int st = 0;
    for (int kt = 0; kt < NKT; kt++) {
        if (kt < NKT - 1) cp_wait<1>(); else cp_wait<0>();
        __syncthreads();
        if (kt + 2 < NKT) {
            int ns = st + 2; if (ns >= 3) ns -= 3;
            const size_t koff = base + (size_t)((kt + 2) * 128) * QKV_N;
            load_tile72_async(s.Kh[ns], qkv_hi + koff + DIM,     tid);
            load_tile72_async(s.Vh[ns], qkv_hi + koff + 2 * DIM, tid);
            cp_commit();
        }

#pragma unroll
        for (int rg = 0; rg < 2; rg++) {
            float S[16][4];
#pragma unroll
            for (int j = 0; j < 16; j++)
#pragma unroll
                for (int q = 0; q < 4; q++) S[j][q] = 0.f;

#pragma unroll
            for (int kc = 0; kc < 4; kc++) {
#pragma unroll
                for (int np = 0; np < 8; np++) {
                    uint32_t kh[4];
                    int r = 16 * np + (lane & 7) + (lane >> 4) * 8;
                    int c = 16 * kc + ((lane >> 3) & 1) * 8;
                    ldsm4(kh, sptr(&s.Kh[st][r][c]));
                    mma_f16(S[2 * np + 0], qh[rg][kc], kh[0], kh[1]);
                    mma_f16(S[2 * np + 1], qh[rg][kc], kh[2], kh[3]);
                }
            }

#pragma unroll
            for (int j = 0; j < 16; j++) {
#pragma unroll
                for (int q = 0; q < 4; q++) {
                    float z = S[j][q] * ATT_SCALE;
                    float p = fmaf(fmaf(av, z, bv), z, gv);
                    S[j][q] = fmaxf(p, 0.f);
                }
                rs[rg][0] += S[j][0] + S[j][1];
                rs[rg][1] += S[j][2] + S[j][3];
            }

#pragma unroll
            for (int c8 = 0; c8 < 8; c8++) {
                uint32_t ph[4];
                ph[0] = pack_h(S[2 * c8][0],     S[2 * c8][1]);
                ph[1] = pack_h(S[2 * c8][2],     S[2 * c8][3]);
                ph[2] = pack_h(S[2 * c8 + 1][0], S[2 * c8 + 1][1]);
                ph[3] = pack_h(S[2 * c8 + 1][2], S[2 * c8 + 1][3]);
#pragma unroll
                for (int ep = 0; ep < 4; ep++) {
                    uint32_t vh[4];
                    int r = 16 * c8 + (lane & 7) + ((lane >> 3) & 1) * 8;
                    int c = 16 * ep + (lane >> 4) * 8;
                    ldsm4t(vh, sptr(&s.Vh[st][r][c]));
                    mma_f16(O[rg][2 * ep + 0], ph, vh[0], vh[1]);
                    mma_f16(O[rg][2 * ep + 1], ph, vh[2], vh[3]);
                }
            }
        }
        if (++st == 3) st = 0;
    }

#pragma unroll
    for (int rg = 0; rg < 2; rg++) {
        float r0 = rs[rg][0], r1 = rs[rg][1];
        r0 += __shfl_xor_sync(0xffffffffu, r0, 1);
        r0 += __shfl_xor_sync(0xffffffffu, r0, 2);
        r1 += __shfl_xor_sync(0xffffffffu, r1, 1);
        r1 += __shfl_xor_sync(0xffffffffu, r1, 2);
        const float inv0 = 1.f / (r0 + 1e-6f);
        const float inv1 = 1.f / (r1 + 1e-6f);

        const int row = b * SEQ + q0 + 32 * w + 16 * rg + (lane >> 2);
#pragma unroll
        for (int j = 0; j < 8; j++) {
            int ce = h * HD + 8 * j + 2 * (lane & 3);
            *reinterpret_cast<uint32_t*>(&att_hi[(size_t)row * DIM + ce]) =
                pack_h(O[rg][j][0] * inv0, O[rg][j][1] * inv0);
            *reinterpret_cast<uint32_t*>(&att_hi[(size_t)(row + 8) * DIM + ce]) =
                pack_h(O[rg][j][2] * inv1, O[rg][j][3] * inv1);
        }
    }
}

// ---------------------------------------------------------------------------
// Launch
// ---------------------------------------------------------------------------
extern "C" void kernel_launch(void* const* d_in, const int* in_sizes, int n_in,
                              void* d_out, int out_size)
{
    const float* x      = (const float*)d_in[0];
    const float* w_qkv  = (const float*)d_in[1];
    const float* w_proj = (const float*)d_in[2];
    const float* b_proj = (const float*)d_in[3];
    const float* alpha  = (const float*)d_in[4];
    const float* beta   = (const float*)d_in[5];
    const float* gamma  = (const float*)d_in[6];
    float* out = (float*)d_out;

    __half *xh, *wqh, *wph, *qh, *ah;
    cudaGetSymbolAddress((void**)&xh,  g_x_hi);
    cudaGetSymbolAddress((void**)&wqh, g_wqkv_hi);
    cudaGetSymbolAddress((void**)&wph, g_wproj_hi);
    cudaGetSymbolAddress((void**)&qh,  g_qkv_hi);
    cudaGetSymbolAddress((void**)&ah,  g_att_hi);

    cudaFuncSetAttribute((const void*)gemm_f16<1, 128, 3>,
                         cudaFuncAttributeMaxDynamicSharedMemorySize,
                         (int)sizeof(GemmSmemT<128, 3>));
    cudaFuncSetAttribute((const void*)gemm_f16<0, 64, 2>,
                         cudaFuncAttributeMaxDynamicSharedMemorySize,
                         (int)sizeof(GemmSmemT<64, 2>));
    cudaFuncSetAttribute((const void*)attn_mma,
                         cudaFuncAttributeMaxDynamicSharedMemorySize,
                         (int)sizeof(AttnSmem));

    // 0) fp32 -> fp16 planes, one launch for all three tensors
    to_half_all<<<N4_ALL / 256, 256>>>((const float4*)x, (const float4*)w_qkv,
                                       (const float4*)w_proj,
                                       (uint2*)xh, (uint2*)wqh, (uint2*)wph);

    // 1) QKV projection -> fp16 plane (128x128, 3-stage, 1 sync/chunk)
    {
        dim3 grid(QKV_N / 128, M_TOT / 128);
        gemm_f16<1, 128, 3><<<grid, 256, sizeof(GemmSmemT<128, 3>)>>>(
            xh, wqh, nullptr, qh, nullptr, M_TOT, QKV_N, DIM);
    }

    // 2) Fused quadratic attention -> fp16 plane (3-stage K/V)
    {
        dim3 grid(SEQ / QB, NH, BB);
        attn_mma<<<grid, 256, sizeof(AttnSmem)>>>(qh, alpha, beta, gamma, ah);
    }

    // 3) Output projection + bias -> fp32 out (64x128, 2-stage, occ 3)
    {
        dim3 grid(DIM / 128, M_TOT / 64);
        gemm_f16<0, 64, 2><<<grid, 256, sizeof(GemmSmemT<64, 2>)>>>(
            ah, wph, b_proj, nullptr, out, M_TOT, DIM, DIM);
    }
}